// round 3
// baseline (speedup 1.0000x reference)
#include <cuda_runtime.h>

#define TT 300
#define NB 4

// ---------------- static device buffers ----------------
__device__ unsigned long long g_r0[TT*NB*2*34];                  // input row masks, bit (x+2)
__device__ __align__(16) unsigned int g_M1[TT*NB*1156];          // spikes L1: 24ch bits / pixel
__device__ unsigned int g_M2[TT*NB*289];                         // spikes P1
__device__ __align__(16) unsigned int g_M3[TT*NB*289*2];         // spikes L2: 48ch in 2 words
__device__ unsigned int g_M4[TT*NB*81*2];                        // spikes P2
__device__ __align__(16) unsigned int g_M5[TT*NB*81*3];          // spikes L3: 96ch in 3 words
__device__ unsigned int g_M6[TT*NB*25*3];                        // spikes P3
__device__ __align__(16) unsigned int g_M7[TT*NB*8];             // spikes dense1: 256 bits

__device__ float g_A1[(size_t)TT*NB*1156*32];                    // conv1 pre-act (pad 24->32)
__device__ float g_A2[(size_t)TT*NB*289*64];                     // conv2 pre-act (pad 48->64)
__device__ float g_A3[(size_t)TT*NB*81*96];                      // conv3 pre-act
__device__ float g_A7[TT*NB*256];                                // dense1 pre-act
__device__ float g_A8T[NB*16*TT];                                // dense2 pre-act, [b][o][t]

__device__ float  g_Wt1[50*32];     // [(ky*10 + c*5+kx)][o pad32]
__device__ float2 g_Wt2p[216*32];   // [(c*9+kt)][lane] -> (o=lane, o=lane+32)
__device__ float4 g_Wt3p[432*32];   // [(c*9+kt)][lane] -> (o=lane, +32, +64, pad)
__device__ float  g_Wt4[2400*256];  // [(c*25+pos)][o 256]
__device__ float  g_Wt5[256*16];    // [i][o pad16]

// ---------------- SRM step: psp (tau=10) + spike w/ refractory (tau=1) ----------------
__device__ __forceinline__ float srm_step(float& p1, float& q1, float& p2, float& q2, float x) {
    const float A1 = 0.90483741803595952f;   // exp(-1/10)
    const float C1 = 0.27182818284590452f;   // e/10
    const float A2 = 0.36787944117144233f;   // exp(-1)
    const float C2 = 2.71828182845904523f;   // e
    const float RR = 20.0f * C2;             // SCALE_REF*THETA*c
    q1 = A1*q1 + A1*p1;
    p1 = A1*p1 + x;
    float y = C1 * q1;
    q2 = A2*q2 + A2*p2;
    float u = y - RR*q2;
    float s = (u >= 10.0f) ? 1.0f : 0.0f;
    p2 = A2*p2 + s;
    return s;
}

// ---------------- SRM scan, 4 neuron-groups per warp (4 indep chains / thread) ----------------
__device__ __forceinline__ void srm_scan4_body(const float* __restrict__ in,
                                               unsigned int* __restrict__ out, int nW) {
    int warp = blockIdx.x * (blockDim.x >> 5) + (threadIdx.x >> 5);
    int lane = threadIdx.x & 31;
    int w0 = warp * 4;
    if (w0 >= nW) return;
    const float* ip = in + (size_t)w0*32 + lane;
    size_t S = (size_t)nW * 32;
    const int PF = 4;
    float buf[PF][4];
#pragma unroll
    for (int k = 0; k < PF; k++)
#pragma unroll
        for (int j = 0; j < 4; j++)
            buf[k][j] = ip[(size_t)k*S + j*32];
    float p1[4] = {0,0,0,0}, q1[4] = {0,0,0,0}, p2[4] = {0,0,0,0}, q2[4] = {0,0,0,0};
    for (int t0 = 0; t0 < TT; t0 += PF) {
#pragma unroll
        for (int k = 0; k < PF; k++) {
            int t = t0 + k;
            unsigned bal0, bal1, bal2, bal3;
#pragma unroll
            for (int j = 0; j < 4; j++) {
                float x = buf[k][j];
                int tn = t + PF;
                buf[k][j] = (tn < TT) ? ip[(size_t)tn*S + j*32] : 0.f;
                float s = srm_step(p1[j], q1[j], p2[j], q2[j], x);
                unsigned b = __ballot_sync(0xffffffffu, s > 0.5f);
                if (j == 0) bal0 = b; else if (j == 1) bal1 = b;
                else if (j == 2) bal2 = b; else bal3 = b;
            }
            if (lane == 0)
                *(uint4*)(out + (size_t)t*nW + w0) = make_uint4(bal0, bal1, bal2, bal3);
        }
    }
}

__global__ void __launch_bounds__(256) srm_scan_L1() { srm_scan4_body(g_A1, g_M1, NB*1156);  }
__global__ void __launch_bounds__(256) srm_scan_L2() { srm_scan4_body(g_A2, g_M3, NB*289*2); }
__global__ void __launch_bounds__(256) srm_scan_L3() { srm_scan4_body(g_A3, g_M5, NB*81*3);  }
__global__ void __launch_bounds__(256) srm_scan_D1() { srm_scan4_body(g_A7, g_M7, NB*8);     }

// ---------------- weight transpose / pad ----------------
__global__ void prep_weights(const float* __restrict__ Wc1, const float* __restrict__ Wc2,
                             const float* __restrict__ Wc3, const float* __restrict__ Wd4a,
                             const float* __restrict__ Wd4b) {
    int i = blockIdx.x * blockDim.x + threadIdx.x;
    if (i < 50*32) {
        int tap = i >> 5, o = i & 31;
        int ky = tap / 10, bit = tap % 10, c = bit / 5, kx = bit % 5;
        g_Wt1[i] = (o < 24) ? Wc1[o*50 + c*25 + ky*5 + kx] : 0.f;
    }
    if (i < 216*32) {
        int tap = i >> 5, l = i & 31;
        float x = Wc2[l*216 + tap];
        float y = (l < 16) ? Wc2[(l + 32)*216 + tap] : 0.f;
        g_Wt2p[i] = make_float2(x, y);
    }
    if (i < 432*32) {
        int tap = i >> 5, l = i & 31;
        g_Wt3p[i] = make_float4(Wc3[l*432 + tap], Wc3[(l + 32)*432 + tap],
                                Wc3[(l + 64)*432 + tap], 0.f);
    }
    if (i < 2400*256) {
        int r = i >> 8, o = i & 255;
        g_Wt4[i] = Wd4a[o*2400 + r];
    }
    if (i < 256*16) {
        int r = i >> 4, o = i & 15;
        g_Wt5[i] = (o < 10) ? Wd4b[o*256 + r] : 0.f;
    }
}

// ---------------- pack s_in (B,2,34,34,T) -> row bitmasks [t][b][c][y] ----------------
__global__ void pack_input(const float* __restrict__ s_in) {
    int idx = blockIdx.x * blockDim.x + threadIdx.x;
    if (idx >= NB*2*34*TT) return;
    int t = idx % TT;
    int r = idx / TT;
    int y = r % 34; r /= 34;
    int c = r % 2;
    int b = r / 2;
    const float* sp = s_in + ((size_t)((b*2 + c)*34 + y)*34)*TT + t;
    unsigned long long m = 0ull;
    for (int x = 0; x < 34; x++)
        if (sp[(size_t)x*TT] != 0.f) m |= (1ull << (x + 2));
    g_r0[((size_t)(t*NB + b)*2 + c)*34 + y] = m;
}

// ---------------- conv1 acc (2->24, 5x5, pad2): warp per (t,b,pixel) ----------------
__global__ void __launch_bounds__(256) conv1_acc() {
    int gw = blockIdx.x * 8 + (threadIdx.x >> 5);
    int lane = threadIdx.x & 31;
    if (gw >= TT*NB*1156) return;
    int rem = gw % 1156, tb = gw / 1156;
    int y = rem / 34, x = rem % 34;
    const unsigned long long* rt = g_r0 + (size_t)tb*68;
    float acc = 0.f;
#pragma unroll
    for (int ky = 0; ky < 5; ky++) {
        int yy = y + ky - 2;
        unsigned f = 0u;
        if (yy >= 0 && yy < 34)
            f = ((unsigned)(rt[yy] >> x) & 31u) | (((unsigned)(rt[34 + yy] >> x) & 31u) << 5);
        const float* wr = g_Wt1 + ky*320;
        while (f) { int bit = __ffs(f) - 1; f &= f - 1; acc += wr[(bit << 5) + lane]; }
    }
    g_A1[(size_t)gw*32 + lane] = acc;
}

// ---------------- pool1 + SRM fused: warp per (b,opix), lane = ch ----------------
__global__ void __launch_bounds__(256) pool1_srm() {
    int w = blockIdx.x * (blockDim.x >> 5) + (threadIdx.x >> 5);
    int lane = threadIdx.x & 31;
    if (w >= NB*289) return;
    int b = w / 289, pix = w % 289;
    int y = pix / 17, x = pix % 17;
    int p0 = b*1156 + 2*y*34 + 2*x;
    const int PF = 4;
    unsigned buf[PF][4];
#pragma unroll
    for (int k = 0; k < PF; k++) {
        const unsigned* m = g_M1 + (size_t)k*4624 + p0;
        buf[k][0] = m[0]; buf[k][1] = m[1]; buf[k][2] = m[34]; buf[k][3] = m[35];
    }
    float p1 = 0, q1 = 0, p2 = 0, q2 = 0;
    for (int t0 = 0; t0 < TT; t0 += PF) {
#pragma unroll
        for (int k = 0; k < PF; k++) {
            int t = t0 + k;
            int cnt = ((buf[k][0] >> lane) & 1) + ((buf[k][1] >> lane) & 1)
                    + ((buf[k][2] >> lane) & 1) + ((buf[k][3] >> lane) & 1);
            int tn = t + PF;
            if (tn < TT) {
                const unsigned* m = g_M1 + (size_t)tn*4624 + p0;
                buf[k][0] = m[0]; buf[k][1] = m[1]; buf[k][2] = m[34]; buf[k][3] = m[35];
            }
            float s = srm_step(p1, q1, p2, q2, 11.0f * (float)cnt);
            unsigned bal = __ballot_sync(0xffffffffu, s > 0.5f);
            if (!lane) g_M2[(size_t)t*1156 + w] = bal;
        }
    }
}

// ---------------- conv2 acc (24->48, 3x3, pad1, 17x17): warp per (t,b,pixel) ----------------
__global__ void __launch_bounds__(256) conv2_acc() {
    int gw = blockIdx.x * 8 + (threadIdx.x >> 5);
    int lane = threadIdx.x & 31;
    if (gw >= TT*NB*289) return;
    int pix = gw % 289, tb = gw / 289;
    int y = pix / 17, x = pix % 17;
    const unsigned* mm = g_M2 + (size_t)tb*289;
    float aa = 0.f, ab = 0.f;
#pragma unroll
    for (int ky = 0; ky < 3; ky++) {
        int yy = y + ky - 1;
#pragma unroll
        for (int kx = 0; kx < 3; kx++) {
            int xx = x + kx - 1;
            unsigned m = 0u;
            if (yy >= 0 && yy < 17 && xx >= 0 && xx < 17) m = mm[yy*17 + xx];
            int kt = ky*3 + kx;
            while (m) {
                int c = __ffs(m) - 1; m &= m - 1;
                float2 wv = g_Wt2p[(c*9 + kt)*32 + lane];
                aa += wv.x; ab += wv.y;
            }
        }
    }
    g_A2[(size_t)gw*64 + lane]      = aa;
    g_A2[(size_t)gw*64 + lane + 32] = ab;
}

// ---------------- pool2 + SRM fused: warp per (b,opix,half) ----------------
__global__ void __launch_bounds__(256) pool2_srm() {
    int w = blockIdx.x * (blockDim.x >> 5) + (threadIdx.x >> 5);
    int lane = threadIdx.x & 31;
    if (w >= NB*162) return;
    int b = w / 162, r = w % 162, pix = r >> 1, half = r & 1;
    int y = pix / 9, x = pix % 9;
    bool xv = (2*x + 1) < 17, yv = (2*y + 1) < 17;
    int base = b*578 + (2*y*17 + 2*x)*2 + half;
    const int PF = 4;
    unsigned buf[PF][4];
#pragma unroll
    for (int k = 0; k < PF; k++) {
        const unsigned* m = g_M3 + (size_t)k*2312 + base;
        buf[k][0] = m[0];
        buf[k][1] = xv ? m[2] : 0u;
        buf[k][2] = yv ? m[34] : 0u;
        buf[k][3] = (xv && yv) ? m[36] : 0u;
    }
    float p1 = 0, q1 = 0, p2 = 0, q2 = 0;
    for (int t0 = 0; t0 < TT; t0 += PF) {
#pragma unroll
        for (int k = 0; k < PF; k++) {
            int t = t0 + k;
            int cnt = ((buf[k][0] >> lane) & 1) + ((buf[k][1] >> lane) & 1)
                    + ((buf[k][2] >> lane) & 1) + ((buf[k][3] >> lane) & 1);
            int tn = t + PF;
            if (tn < TT) {
                const unsigned* m = g_M3 + (size_t)tn*2312 + base;
                buf[k][0] = m[0];
                buf[k][1] = xv ? m[2] : 0u;
                buf[k][2] = yv ? m[34] : 0u;
                buf[k][3] = (xv && yv) ? m[36] : 0u;
            }
            float s = srm_step(p1, q1, p2, q2, 11.0f * (float)cnt);
            unsigned bal = __ballot_sync(0xffffffffu, s > 0.5f);
            if (!lane) g_M4[(size_t)t*648 + w] = bal;
        }
    }
}

// ---------------- conv3 acc (48->96, 3x3, pad1, 9x9): warp per (t,b,pixel), 3 outs/lane ----------------
__global__ void __launch_bounds__(256) conv3_acc() {
    int gw = blockIdx.x * 8 + (threadIdx.x >> 5);
    int lane = threadIdx.x & 31;
    if (gw >= TT*NB*81) return;
    int pix = gw % 81, tb = gw / 81;
    int y = pix / 9, x = pix % 9;
    const unsigned* mm = g_M4 + (size_t)tb*162;
    float a0 = 0.f, a1 = 0.f, a2 = 0.f;
#pragma unroll
    for (int ky = 0; ky < 3; ky++) {
        int yy = y + ky - 1;
#pragma unroll
        for (int kx = 0; kx < 3; kx++) {
            int xx = x + kx - 1;
            unsigned mlo = 0u, mhi = 0u;
            if (yy >= 0 && yy < 9 && xx >= 0 && xx < 9) {
                mlo = mm[(yy*9 + xx)*2];
                mhi = mm[(yy*9 + xx)*2 + 1];
            }
            int kt = ky*3 + kx;
            while (mlo) {
                int c = __ffs(mlo) - 1; mlo &= mlo - 1;
                float4 wv = g_Wt3p[(c*9 + kt)*32 + lane];
                a0 += wv.x; a1 += wv.y; a2 += wv.z;
            }
            while (mhi) {
                int c = __ffs(mhi) - 1; mhi &= mhi - 1;
                float4 wv = g_Wt3p[((c + 32)*9 + kt)*32 + lane];
                a0 += wv.x; a1 += wv.y; a2 += wv.z;
            }
        }
    }
    g_A3[(size_t)gw*96 + lane]      = a0;
    g_A3[(size_t)gw*96 + lane + 32] = a1;
    g_A3[(size_t)gw*96 + lane + 64] = a2;
}

// ---------------- pool3 + SRM fused: warp per (b,opix,wrd) ----------------
__global__ void __launch_bounds__(256) pool3_srm() {
    int w = blockIdx.x * (blockDim.x >> 5) + (threadIdx.x >> 5);
    int lane = threadIdx.x & 31;
    if (w >= NB*75) return;
    int b = w / 75, r = w % 75, pix = r / 3, wrd = r % 3;
    int y = pix / 5, x = pix % 5;
    bool xv = (2*x + 1) < 9, yv = (2*y + 1) < 9;
    int base = b*243 + (2*y*9 + 2*x)*3 + wrd;
    const int PF = 4;
    unsigned buf[PF][4];
#pragma unroll
    for (int k = 0; k < PF; k++) {
        const unsigned* m = g_M5 + (size_t)k*972 + base;
        buf[k][0] = m[0];
        buf[k][1] = xv ? m[3] : 0u;
        buf[k][2] = yv ? m[27] : 0u;
        buf[k][3] = (xv && yv) ? m[30] : 0u;
    }
    float p1 = 0, q1 = 0, p2 = 0, q2 = 0;
    for (int t0 = 0; t0 < TT; t0 += PF) {
#pragma unroll
        for (int k = 0; k < PF; k++) {
            int t = t0 + k;
            int cnt = ((buf[k][0] >> lane) & 1) + ((buf[k][1] >> lane) & 1)
                    + ((buf[k][2] >> lane) & 1) + ((buf[k][3] >> lane) & 1);
            int tn = t + PF;
            if (tn < TT) {
                const unsigned* m = g_M5 + (size_t)tn*972 + base;
                buf[k][0] = m[0];
                buf[k][1] = xv ? m[3] : 0u;
                buf[k][2] = yv ? m[27] : 0u;
                buf[k][3] = (xv && yv) ? m[30] : 0u;
            }
            float s = srm_step(p1, q1, p2, q2, 11.0f * (float)cnt);
            unsigned bal = __ballot_sync(0xffffffffu, s > 0.5f);
            if (!lane) g_M6[(size_t)t*300 + w] = bal;
        }
    }
}

// ---------------- dense1 (2400->256): block per (t,b) ----------------
__global__ void __launch_bounds__(256) dense1() {
    int tb = blockIdx.x;
    int o = threadIdx.x;
    const unsigned* m = g_M6 + (size_t)tb*75;
    float acc = 0.f;
    for (int pos = 0; pos < 25; pos++)
        for (int wd = 0; wd < 3; wd++) {
            unsigned mm = m[pos*3 + wd];
            const float* wt = g_Wt4 + pos*256 + o;
            int cb = wd*32;
            while (mm) { int c = cb + __ffs(mm) - 1; mm &= mm - 1; acc += wt[(size_t)c*6400]; }
        }
    g_A7[(size_t)tb*256 + o] = acc;
}

// ---------------- dense2 (256->10): warp per (t,b), writes transposed ----------------
__global__ void __launch_bounds__(256) dense2() {
    int w = blockIdx.x * 8 + (threadIdx.x >> 5);
    int lane = threadIdx.x & 31;
    if (w >= TT*NB) return;
    int t = w / NB, b = w % NB;
    if (lane < 16) {
        const unsigned* m = g_M7 + (size_t)w*8;
        float acc = 0.f;
        for (int wd = 0; wd < 8; wd++) {
            unsigned mm = m[wd];
            int ib = wd*32;
            while (mm) { int i = ib + __ffs(mm) - 1; mm &= mm - 1; acc += g_Wt5[i*16 + lane]; }
        }
        g_A8T[(size_t)(b*16 + lane)*TT + t] = acc;
    }
}

// ---------------- final SRM -> output spikes (B,10,T) ----------------
__global__ void srm_out(float* __restrict__ out) {
    int tid = threadIdx.x;
    if (tid >= 40) return;
    int b = tid / 10, o = tid % 10;
    const float* ip = g_A8T + (size_t)(b*16 + o)*TT;
    const int PF = 8;
    float buf[PF];
#pragma unroll
    for (int k = 0; k < PF; k++) buf[k] = ip[k];
    float p1 = 0, q1 = 0, p2 = 0, q2 = 0;
    float* op = out + (size_t)(b*10 + o)*TT;
    for (int t0 = 0; t0 < TT; t0 += PF) {
#pragma unroll
        for (int k = 0; k < PF; k++) {
            int t = t0 + k;
            if (t >= TT) break;
            float x = buf[k];
            int tn = t + PF;
            buf[k] = (tn < TT) ? ip[tn] : 0.f;
            op[t] = srm_step(p1, q1, p2, q2, x);
        }
    }
}

extern "C" void kernel_launch(void* const* d_in, const int* in_sizes, int n_in,
                              void* d_out, int out_size) {
    const float* s_in = (const float*)d_in[0];
    const float* Wc1  = (const float*)d_in[1];
    const float* Wc2  = (const float*)d_in[2];
    const float* Wc3  = (const float*)d_in[3];
    const float* Wd4a = (const float*)d_in[4];
    const float* Wd4b = (const float*)d_in[5];
    float* out = (float*)d_out;

    prep_weights<<<2400, 256>>>(Wc1, Wc2, Wc3, Wd4a, Wd4b);
    pack_input<<<(NB*2*34*TT + 255)/256, 256>>>(s_in);

    conv1_acc<<<(TT*NB*1156 + 7)/8, 256>>>();
    srm_scan_L1<<<(NB*1156/4*32 + 255)/256, 256>>>();

    pool1_srm<<<(NB*289*32 + 255)/256, 256>>>();

    conv2_acc<<<(TT*NB*289 + 7)/8, 256>>>();
    srm_scan_L2<<<(NB*289*2/4*32 + 255)/256, 256>>>();

    pool2_srm<<<(NB*162*32 + 255)/256, 256>>>();

    conv3_acc<<<(TT*NB*81 + 7)/8, 256>>>();
    srm_scan_L3<<<(NB*81*3/4*32 + 255)/256, 256>>>();

    pool3_srm<<<(NB*75*32 + 255)/256, 256>>>();

    dense1<<<TT*NB, 256>>>();
    srm_scan_D1<<<1, 256>>>();

    dense2<<<(TT*NB + 7)/8, 256>>>();
    srm_out<<<1, 64>>>(out);
}

// round 6
// speedup vs baseline: 1.1837x; 1.1837x over previous
#include <cuda_runtime.h>

#define TT 300
#define NB 4

// ---------------- static device buffers (padded for unconditional prefetch) ----------------
__device__ unsigned long long g_r0[TT*NB*2*34];                      // input row masks, bit (x+2)
__device__ unsigned int g_M1[(TT+4)*NB*1156];                        // spikes L1: 24ch bits / pixel
__device__ unsigned int g_M2[TT*NB*289];                             // spikes P1
__device__ unsigned int g_M3[(TT+4)*NB*289*2];                       // spikes L2: 48ch in 2 words
__device__ unsigned int g_M4[TT*NB*81*2];                            // spikes P2
__device__ unsigned int g_M5[(TT+4)*NB*81*3];                        // spikes L3: 96ch in 3 words
__device__ unsigned int g_M6[TT*NB*25*3];                            // spikes P3
__device__ unsigned int g_M7[TT*NB*8];                               // spikes dense1: 256 bits

__device__ float g_A1[(size_t)(TT+8)*NB*1156*32];                    // conv1 pre-act (pad 24->32)
__device__ float g_A2[(size_t)(TT+8)*NB*289*64];                     // conv2 pre-act (pad 48->64)
__device__ float g_A3[(size_t)(TT+8)*NB*81*96];                      // conv3 pre-act
__device__ float g_A7[(TT+8)*NB*256];                                // dense1 pre-act
__device__ float g_A8T[NB*16*TT];                                    // dense2 pre-act, [b][o][t]

__device__ float  g_Wt1[50*32];     // [(ky*10 + c*5+kx)][o pad32]
__device__ float2 g_Wt2p[216*32];   // [(c*9+kt)][lane] -> (o=lane, o=lane+32)
__device__ float4 g_Wt3p[432*32];   // [(c*9+kt)][lane] -> (o=lane, +32, +64, pad)
__device__ float  g_Wt4[2400*256];  // [(c*25+pos)][o 256]
__device__ float  g_Wt5[256*16];    // [i][o pad16]

// ---------------- SRM step: psp (tau=10) + spike w/ refractory (tau=1) ----------------
__device__ __forceinline__ float srm_step(float& p1, float& q1, float& p2, float& q2, float x) {
    const float A1 = 0.90483741803595952f;   // exp(-1/10)
    const float C1 = 0.27182818284590452f;   // e/10
    const float A2 = 0.36787944117144233f;   // exp(-1)
    const float C2 = 2.71828182845904523f;   // e
    const float RR = 20.0f * C2;             // SCALE_REF*THETA*c
    q1 = A1*q1 + A1*p1;
    p1 = A1*p1 + x;
    float y = C1 * q1;
    q2 = A2*q2 + A2*p2;
    float u = y - RR*q2;
    float s = (u >= 10.0f) ? 1.0f : 0.0f;
    p2 = A2*p2 + s;
    return s;
}

// ---------------- SRM scan: warp = 32 neurons, PF=8 ring, clean main loop + tail ----------------
__device__ __forceinline__ void srm_scan_body(const float* __restrict__ in,
                                              unsigned int* __restrict__ out, int nW) {
    int w = blockIdx.x * (blockDim.x >> 5) + (threadIdx.x >> 5);
    int lane = threadIdx.x & 31;
    if (w >= nW) return;
    const float* ip = in + (size_t)w*32 + lane;
    size_t S = (size_t)nW * 32;
    const int PF = 8;
    float buf[PF];
#pragma unroll
    for (int k = 0; k < PF; k++) buf[k] = ip[(size_t)k*S];
    float p1=0,q1=0,p2=0,q2=0;
#pragma unroll 1
    for (int t0 = 0; t0 < 296; t0 += PF) {
#pragma unroll
        for (int k = 0; k < PF; k++) {
            int t = t0 + k;
            float x = buf[k];
            buf[k] = ip[(size_t)(t + PF)*S];            // padded: always valid
            float s = srm_step(p1, q1, p2, q2, x);
            unsigned bal = __ballot_sync(0xffffffffu, s > 0.5f);
            if (!lane) out[(size_t)t*nW + w] = bal;
        }
    }
#pragma unroll
    for (int k = 0; k < 4; k++) {                       // t = 296..299
        float s = srm_step(p1, q1, p2, q2, buf[k]);
        unsigned bal = __ballot_sync(0xffffffffu, s > 0.5f);
        if (!lane) out[(size_t)(296 + k)*nW + w] = bal;
    }
}

__global__ void __launch_bounds__(256) srm_scan_L1() { srm_scan_body(g_A1, g_M1, NB*1156);  }
__global__ void __launch_bounds__(256) srm_scan_L2() { srm_scan_body(g_A2, g_M3, NB*289*2); }
__global__ void __launch_bounds__(256) srm_scan_L3() { srm_scan_body(g_A3, g_M5, NB*81*3);  }
__global__ void __launch_bounds__(256) srm_scan_D1() { srm_scan_body(g_A7, g_M7, NB*8);     }

// ---------------- init: weight transpose/pad + input bit-pack (merged) ----------------
__global__ void init_all(const float* __restrict__ Wc1, const float* __restrict__ Wc2,
                         const float* __restrict__ Wc3, const float* __restrict__ Wd4a,
                         const float* __restrict__ Wd4b, const float* __restrict__ s_in) {
    int bid = blockIdx.x;
    if (bid < 2400) {
        int i = bid * 256 + threadIdx.x;
        if (i < 50*32) {
            int tap = i >> 5, o = i & 31;
            int ky = tap / 10, bit = tap % 10, c = bit / 5, kx = bit % 5;
            g_Wt1[i] = (o < 24) ? Wc1[o*50 + c*25 + ky*5 + kx] : 0.f;
        }
        if (i < 216*32) {
            int tap = i >> 5, l = i & 31;
            float x = Wc2[l*216 + tap];
            float y = (l < 16) ? Wc2[(l + 32)*216 + tap] : 0.f;
            g_Wt2p[i] = make_float2(x, y);
        }
        if (i < 432*32) {
            int tap = i >> 5, l = i & 31;
            g_Wt3p[i] = make_float4(Wc3[l*432 + tap], Wc3[(l + 32)*432 + tap],
                                    Wc3[(l + 64)*432 + tap], 0.f);
        }
        if (i < 2400*256) {
            int r = i >> 8, o = i & 255;
            g_Wt4[i] = Wd4a[o*2400 + r];
        }
        if (i < 256*16) {
            int r = i >> 4, o = i & 15;
            g_Wt5[i] = (o < 10) ? Wd4b[o*256 + r] : 0.f;
        }
    } else {
        int idx = (bid - 2400) * 256 + threadIdx.x;
        if (idx >= NB*2*34*TT) return;
        int t = idx % TT;
        int r = idx / TT;
        int y = r % 34; r /= 34;
        int c = r % 2;
        int b = r / 2;
        const float* sp = s_in + ((size_t)((b*2 + c)*34 + y)*34)*TT + t;
        unsigned long long m = 0ull;
        for (int x = 0; x < 34; x++)
            if (sp[(size_t)x*TT] != 0.f) m |= (1ull << (x + 2));
        g_r0[((size_t)(t*NB + b)*2 + c)*34 + y] = m;
    }
}

// ---------------- conv1 acc (2->24, 5x5, pad2): warp per (t,b,x-pair) ----------------
__global__ void __launch_bounds__(256) conv1_acc() {
    int gw = blockIdx.x * 8 + (threadIdx.x >> 5);
    int lane = threadIdx.x & 31;
    if (gw >= TT*NB*578) return;
    int pr = gw % 578, tb = gw / 578;
    int y = pr / 17, x0 = (pr % 17) * 2;
    const unsigned long long* rt = g_r0 + (size_t)tb*68;
    float acc0 = 0.f, acc1 = 0.f;
#pragma unroll
    for (int ky = 0; ky < 5; ky++) {
        int yy = y + ky - 2;
        if (yy < 0 || yy >= 34) continue;
        unsigned long long ra = rt[yy], rb = rt[34 + yy];
        unsigned f0 = ((unsigned)(ra >> x0) & 31u) | (((unsigned)(rb >> x0) & 31u) << 5);
        unsigned f1 = ((unsigned)(ra >> (x0+1)) & 31u) | (((unsigned)(rb >> (x0+1)) & 31u) << 5);
        const float* wr = g_Wt1 + ky*320;
        while (f0) { int b = __ffs(f0) - 1; f0 &= f0 - 1; acc0 += wr[(b << 5) + lane]; }
        while (f1) { int b = __ffs(f1) - 1; f1 &= f1 - 1; acc1 += wr[(b << 5) + lane]; }
    }
    size_t base = ((size_t)tb*1156 + y*34 + x0)*32;
    g_A1[base + lane]      = acc0;
    g_A1[base + 32 + lane] = acc1;
}

// ---------------- pool1 + SRM fused: warp per (b,opix), lane = ch ----------------
__global__ void __launch_bounds__(256) pool1_srm() {
    int w = blockIdx.x * (blockDim.x >> 5) + (threadIdx.x >> 5);
    int lane = threadIdx.x & 31;
    if (w >= NB*289) return;
    int b = w / 289, pix = w % 289;
    int y = pix / 17, x = pix % 17;
    int p0 = b*1156 + 2*y*34 + 2*x;
    const int PF = 4;
    unsigned buf[PF][4];
#pragma unroll
    for (int k = 0; k < PF; k++) {
        const unsigned* m = g_M1 + (size_t)k*4624 + p0;
        buf[k][0] = m[0]; buf[k][1] = m[1]; buf[k][2] = m[34]; buf[k][3] = m[35];
    }
    float p1 = 0, q1 = 0, p2 = 0, q2 = 0;
#pragma unroll 1
    for (int t0 = 0; t0 < TT; t0 += PF) {
#pragma unroll
        for (int k = 0; k < PF; k++) {
            int t = t0 + k;
            int cnt = ((buf[k][0] >> lane) & 1) + ((buf[k][1] >> lane) & 1)
                    + ((buf[k][2] >> lane) & 1) + ((buf[k][3] >> lane) & 1);
            const unsigned* m = g_M1 + (size_t)(t + PF)*4624 + p0;   // padded
            buf[k][0] = m[0]; buf[k][1] = m[1]; buf[k][2] = m[34]; buf[k][3] = m[35];
            float s = srm_step(p1, q1, p2, q2, 11.0f * (float)cnt);
            unsigned bal = __ballot_sync(0xffffffffu, s > 0.5f);
            if (!lane) g_M2[(size_t)t*1156 + w] = bal;
        }
    }
}

// ---------------- conv2 acc (24->48, 3x3, pad1, 17x17): warp per (t,b,pixel) ----------------
__global__ void __launch_bounds__(256) conv2_acc() {
    int gw = blockIdx.x * 8 + (threadIdx.x >> 5);
    int lane = threadIdx.x & 31;
    if (gw >= TT*NB*289) return;
    int pix = gw % 289, tb = gw / 289;
    int y = pix / 17, x = pix % 17;
    const unsigned* mm = g_M2 + (size_t)tb*289;
    float aa = 0.f, ab = 0.f;
#pragma unroll
    for (int ky = 0; ky < 3; ky++) {
        int yy = y + ky - 1;
#pragma unroll
        for (int kx = 0; kx < 3; kx++) {
            int xx = x + kx - 1;
            unsigned m = 0u;
            if (yy >= 0 && yy < 17 && xx >= 0 && xx < 17) m = mm[yy*17 + xx];
            int kt = ky*3 + kx;
            while (m) {
                int c = __ffs(m) - 1; m &= m - 1;
                float2 wv = g_Wt2p[(c*9 + kt)*32 + lane];
                aa += wv.x; ab += wv.y;
            }
        }
    }
    g_A2[(size_t)gw*64 + lane]      = aa;
    g_A2[(size_t)gw*64 + lane + 32] = ab;
}

// ---------------- pool2 + SRM fused: warp per (b,opix,half) ----------------
__global__ void __launch_bounds__(256) pool2_srm() {
    int w = blockIdx.x * (blockDim.x >> 5) + (threadIdx.x >> 5);
    int lane = threadIdx.x & 31;
    if (w >= NB*162) return;
    int b = w / 162, r = w % 162, pix = r >> 1, half = r & 1;
    int y = pix / 9, x = pix % 9;
    bool xv = (2*x + 1) < 17, yv = (2*y + 1) < 17;
    int base = b*578 + (2*y*17 + 2*x)*2 + half;
    const int PF = 4;
    unsigned buf[PF][4];
#pragma unroll
    for (int k = 0; k < PF; k++) {
        const unsigned* m = g_M3 + (size_t)k*2312 + base;
        buf[k][0] = m[0];
        buf[k][1] = xv ? m[2] : 0u;
        buf[k][2] = yv ? m[34] : 0u;
        buf[k][3] = (xv && yv) ? m[36] : 0u;
    }
    float p1 = 0, q1 = 0, p2 = 0, q2 = 0;
#pragma unroll 1
    for (int t0 = 0; t0 < TT; t0 += PF) {
#pragma unroll
        for (int k = 0; k < PF; k++) {
            int t = t0 + k;
            int cnt = ((buf[k][0] >> lane) & 1) + ((buf[k][1] >> lane) & 1)
                    + ((buf[k][2] >> lane) & 1) + ((buf[k][3] >> lane) & 1);
            const unsigned* m = g_M3 + (size_t)(t + PF)*2312 + base;  // padded
            buf[k][0] = m[0];
            buf[k][1] = xv ? m[2] : 0u;
            buf[k][2] = yv ? m[34] : 0u;
            buf[k][3] = (xv && yv) ? m[36] : 0u;
            float s = srm_step(p1, q1, p2, q2, 11.0f * (float)cnt);
            unsigned bal = __ballot_sync(0xffffffffu, s > 0.5f);
            if (!lane) g_M4[(size_t)t*648 + w] = bal;
        }
    }
}

// ---------------- conv3 acc (48->96, 3x3, pad1, 9x9): warp per (t,b,pixel), 3 outs/lane ----------------
__global__ void __launch_bounds__(256) conv3_acc() {
    int gw = blockIdx.x * 8 + (threadIdx.x >> 5);
    int lane = threadIdx.x & 31;
    if (gw >= TT*NB*81) return;
    int pix = gw % 81, tb = gw / 81;
    int y = pix / 9, x = pix % 9;
    const unsigned* mm = g_M4 + (size_t)tb*162;
    float a0 = 0.f, a1 = 0.f, a2 = 0.f;
#pragma unroll
    for (int ky = 0; ky < 3; ky++) {
        int yy = y + ky - 1;
#pragma unroll
        for (int kx = 0; kx < 3; kx++) {
            int xx = x + kx - 1;
            unsigned mlo = 0u, mhi = 0u;
            if (yy >= 0 && yy < 9 && xx >= 0 && xx < 9) {
                mlo = mm[(yy*9 + xx)*2];
                mhi = mm[(yy*9 + xx)*2 + 1];
            }
            int kt = ky*3 + kx;
            while (mlo) {
                int c = __ffs(mlo) - 1; mlo &= mlo - 1;
                float4 wv = g_Wt3p[(c*9 + kt)*32 + lane];
                a0 += wv.x; a1 += wv.y; a2 += wv.z;
            }
            while (mhi) {
                int c = __ffs(mhi) - 1; mhi &= mhi - 1;
                float4 wv = g_Wt3p[((c + 32)*9 + kt)*32 + lane];
                a0 += wv.x; a1 += wv.y; a2 += wv.z;
            }
        }
    }
    g_A3[(size_t)gw*96 + lane]      = a0;
    g_A3[(size_t)gw*96 + lane + 32] = a1;
    g_A3[(size_t)gw*96 + lane + 64] = a2;
}

// ---------------- pool3 + SRM fused: warp per (b,opix,wrd) ----------------
__global__ void __launch_bounds__(256) pool3_srm() {
    int w = blockIdx.x * (blockDim.x >> 5) + (threadIdx.x >> 5);
    int lane = threadIdx.x & 31;
    if (w >= NB*75) return;
    int b = w / 75, r = w % 75, pix = r / 3, wrd = r % 3;
    int y = pix / 5, x = pix % 5;
    bool xv = (2*x + 1) < 9, yv = (2*y + 1) < 9;
    int base = b*243 + (2*y*9 + 2*x)*3 + wrd;
    const int PF = 4;
    unsigned buf[PF][4];
#pragma unroll
    for (int k = 0; k < PF; k++) {
        const unsigned* m = g_M5 + (size_t)k*972 + base;
        buf[k][0] = m[0];
        buf[k][1] = xv ? m[3] : 0u;
        buf[k][2] = yv ? m[27] : 0u;
        buf[k][3] = (xv && yv) ? m[30] : 0u;
    }
    float p1 = 0, q1 = 0, p2 = 0, q2 = 0;
#pragma unroll 1
    for (int t0 = 0; t0 < TT; t0 += PF) {
#pragma unroll
        for (int k = 0; k < PF; k++) {
            int t = t0 + k;
            int cnt = ((buf[k][0] >> lane) & 1) + ((buf[k][1] >> lane) & 1)
                    + ((buf[k][2] >> lane) & 1) + ((buf[k][3] >> lane) & 1);
            const unsigned* m = g_M5 + (size_t)(t + PF)*972 + base;   // padded
            buf[k][0] = m[0];
            buf[k][1] = xv ? m[3] : 0u;
            buf[k][2] = yv ? m[27] : 0u;
            buf[k][3] = (xv && yv) ? m[30] : 0u;
            float s = srm_step(p1, q1, p2, q2, 11.0f * (float)cnt);
            unsigned bal = __ballot_sync(0xffffffffu, s > 0.5f);
            if (!lane) g_M6[(size_t)t*300 + w] = bal;
        }
    }
}

// ---------------- dense1 (2400->256): block per (t,b) ----------------
__global__ void __launch_bounds__(256) dense1() {
    int tb = blockIdx.x;
    int o = threadIdx.x;
    const unsigned* m = g_M6 + (size_t)tb*75;
    float acc = 0.f;
    for (int pos = 0; pos < 25; pos++)
        for (int wd = 0; wd < 3; wd++) {
            unsigned mm = m[pos*3 + wd];
            const float* wt = g_Wt4 + pos*256 + o;
            int cb = wd*32;
            while (mm) { int c = cb + __ffs(mm) - 1; mm &= mm - 1; acc += wt[(size_t)c*6400]; }
        }
    g_A7[(size_t)tb*256 + o] = acc;
}

// ---------------- dense2 (256->10): warp per (t,b), writes transposed ----------------
__global__ void __launch_bounds__(256) dense2() {
    int w = blockIdx.x * 8 + (threadIdx.x >> 5);
    int lane = threadIdx.x & 31;
    if (w >= TT*NB) return;
    int t = w / NB, b = w % NB;
    if (lane < 16) {
        const unsigned* m = g_M7 + (size_t)w*8;
        float acc = 0.f;
        for (int wd = 0; wd < 8; wd++) {
            unsigned mm = m[wd];
            int ib = wd*32;
            while (mm) { int i = ib + __ffs(mm) - 1; mm &= mm - 1; acc += g_Wt5[i*16 + lane]; }
        }
        g_A8T[(size_t)(b*16 + lane)*TT + t] = acc;
    }
}

// ---------------- final SRM -> output spikes (B,10,T) ----------------
__global__ void srm_out(float* __restrict__ out) {
    int tid = threadIdx.x;
    if (tid >= 40) return;
    int b = tid / 10, o = tid % 10;
    const float* ip = g_A8T + (size_t)(b*16 + o)*TT;
    const int PF = 8;
    float buf[PF];
#pragma unroll
    for (int k = 0; k < PF; k++) buf[k] = ip[k];
    float p1 = 0, q1 = 0, p2 = 0, q2 = 0;
    float* op = out + (size_t)(b*10 + o)*TT;
    for (int t0 = 0; t0 < TT; t0 += PF) {
#pragma unroll
        for (int k = 0; k < PF; k++) {
            int t = t0 + k;
            if (t >= TT) break;
            float x = buf[k];
            int tn = t + PF;
            buf[k] = (tn < TT) ? ip[tn] : 0.f;
            op[t] = srm_step(p1, q1, p2, q2, x);
        }
    }
}

extern "C" void kernel_launch(void* const* d_in, const int* in_sizes, int n_in,
                              void* d_out, int out_size) {
    const float* s_in = (const float*)d_in[0];
    const float* Wc1  = (const float*)d_in[1];
    const float* Wc2  = (const float*)d_in[2];
    const float* Wc3  = (const float*)d_in[3];
    const float* Wd4a = (const float*)d_in[4];
    const float* Wd4b = (const float*)d_in[5];
    float* out = (float*)d_out;

    init_all<<<2400 + (NB*2*34*TT + 255)/256, 256>>>(Wc1, Wc2, Wc3, Wd4a, Wd4b, s_in);

    conv1_acc<<<(TT*NB*578 + 7)/8, 256>>>();
    srm_scan_L1<<<(NB*1156 + 7)/8, 256>>>();
    pool1_srm<<<(NB*289*32 + 255)/256, 256>>>();

    conv2_acc<<<(TT*NB*289 + 7)/8, 256>>>();
    srm_scan_L2<<<(NB*289*2 + 7)/8, 256>>>();
    pool2_srm<<<(NB*162*32 + 255)/256, 256>>>();

    conv3_acc<<<(TT*NB*81 + 7)/8, 256>>>();
    srm_scan_L3<<<(NB*81*3 + 7)/8, 256>>>();
    pool3_srm<<<(NB*75*32 + 255)/256, 256>>>();

    dense1<<<TT*NB, 256>>>();
    srm_scan_D1<<<(NB*8 + 7)/8, 256>>>();

    dense2<<<(TT*NB + 7)/8, 256>>>();
    srm_out<<<1, 64>>>(out);
}

// round 7
// speedup vs baseline: 1.2510x; 1.0569x over previous
#include <cuda_runtime.h>

#define TT 300
#define NB 4

// ---------------- static device buffers (masks padded +8 planes for prefetch) ----------------
__device__ unsigned long long g_r0[TT*NB*2*34];                      // input row masks, bit (x+2)
__device__ __align__(16) unsigned int g_M1[(TT+8)*NB*1156];          // spikes L1: 24ch bits / pixel
__device__ unsigned int g_M2[TT*NB*289];                             // spikes P1
__device__ __align__(16) unsigned int g_M3[(TT+8)*NB*289*2];         // spikes L2: 48ch in 2 words
__device__ unsigned int g_M4[TT*NB*81*2];                            // spikes P2
__device__ __align__(16) unsigned int g_M5[(TT+8)*NB*81*3];          // spikes L3: 96ch in 3 words
__device__ unsigned int g_M6[TT*NB*25*3];                            // spikes P3
__device__ unsigned int g_M7[TT*NB*8];                               // spikes dense1: 256 bits

__device__ float g_A1[(size_t)TT*NB*1156*32];                        // conv1 pre-act (pad 24->32)
__device__ float g_A2[(size_t)TT*NB*289*64];                         // conv2 pre-act (pad 48->64)
__device__ float g_A3[(size_t)TT*NB*81*96];                          // conv3 pre-act
__device__ float g_A7[TT*NB*256];                                    // dense1 pre-act
__device__ float g_A8T[NB*16*TT];                                    // dense2 pre-act, [b][o][t]

__device__ float  g_Wt1[50*32];     // [(ky*10 + c*5+kx)][o pad32]
__device__ float2 g_Wt2p[216*32];   // [(c*9+kt)][lane] -> (o=lane, o=lane+32)
__device__ float4 g_Wt3p[432*32];   // [(c*9+kt)][lane] -> (o=lane, +32, +64, pad)
__device__ float  g_Wt4[2400*256];  // [(c*25+pos)][o 256]
__device__ float  g_Wt5[256*16];    // [i][o pad16]

// ---------------- SRM step: psp (tau=10) + spike w/ refractory (tau=1) ----------------
__device__ __forceinline__ float srm_step(float& p1, float& q1, float& p2, float& q2, float x) {
    const float A1 = 0.90483741803595952f;   // exp(-1/10)
    const float C1 = 0.27182818284590452f;   // e/10
    const float A2 = 0.36787944117144233f;   // exp(-1)
    const float C2 = 2.71828182845904523f;   // e
    const float RR = 20.0f * C2;             // SCALE_REF*THETA*c
    q1 = A1*q1 + A1*p1;
    p1 = A1*p1 + x;
    float y = C1 * q1;
    q2 = A2*q2 + A2*p2;
    float u = y - RR*q2;
    float s = (u >= 10.0f) ? 1.0f : 0.0f;
    p2 = A2*p2 + s;
    return s;
}

// ---------------- SRM scan: warp = 32 neurons, PF=12 rolling ring, 512-thr blocks ----------------
__device__ __forceinline__ void srm_scan_body(const float* __restrict__ in,
                                              unsigned int* __restrict__ out, int nW) {
    int w = blockIdx.x * 16 + (threadIdx.x >> 5);
    int lane = threadIdx.x & 31;
    if (w >= nW) return;
    size_t S = (size_t)nW * 32;
    const float* ip = in + (size_t)w*32 + lane;
    const int PF = 12;
    float buf[PF];
#pragma unroll
    for (int k = 0; k < PF; k++) buf[k] = ip[(size_t)k*S];
    const float* pf = ip + (size_t)PF*S;
    unsigned int* op = out + w;
    float p1=0,q1=0,p2=0,q2=0;
#pragma unroll 1
    for (int t0 = 0; t0 < TT - PF; t0 += PF) {          // 288 main steps
#pragma unroll
        for (int k = 0; k < PF; k++) {
            float x = buf[k];
            buf[k] = *pf; pf += S;                       // prefetch t+PF (max 299)
            float s = srm_step(p1, q1, p2, q2, x);
            unsigned bal = __ballot_sync(0xffffffffu, s > 0.5f);
            if (!lane) *op = bal;
            op += nW;
        }
    }
#pragma unroll
    for (int k = 0; k < PF; k++) {                       // t = 288..299
        float s = srm_step(p1, q1, p2, q2, buf[k]);
        unsigned bal = __ballot_sync(0xffffffffu, s > 0.5f);
        if (!lane) *op = bal;
        op += nW;
    }
}

__global__ void __launch_bounds__(512) srm_scan_L1() { srm_scan_body(g_A1, g_M1, NB*1156);  }
__global__ void __launch_bounds__(512) srm_scan_L2() { srm_scan_body(g_A2, g_M3, NB*289*2); }
__global__ void __launch_bounds__(512) srm_scan_L3() { srm_scan_body(g_A3, g_M5, NB*81*3);  }
__global__ void __launch_bounds__(512) srm_scan_D1() { srm_scan_body(g_A7, g_M7, NB*8);     }

// ---------------- init: small weight transposes + input bit-pack ----------------
__global__ void init_all(const float* __restrict__ Wc1, const float* __restrict__ Wc2,
                         const float* __restrict__ Wc3, const float* __restrict__ Wd4b,
                         const float* __restrict__ s_in) {
    int bid = blockIdx.x;
    if (bid < 54) {
        int i = bid * 256 + threadIdx.x;
        if (i < 50*32) {
            int tap = i >> 5, o = i & 31;
            int ky = tap / 10, bit = tap % 10, c = bit / 5, kx = bit % 5;
            g_Wt1[i] = (o < 24) ? Wc1[o*50 + c*25 + ky*5 + kx] : 0.f;
        }
        if (i < 216*32) {
            int tap = i >> 5, l = i & 31;
            float x = Wc2[l*216 + tap];
            float y = (l < 16) ? Wc2[(l + 32)*216 + tap] : 0.f;
            g_Wt2p[i] = make_float2(x, y);
        }
        if (i < 432*32) {
            int tap = i >> 5, l = i & 31;
            g_Wt3p[i] = make_float4(Wc3[l*432 + tap], Wc3[(l + 32)*432 + tap],
                                    Wc3[(l + 64)*432 + tap], 0.f);
        }
        if (i < 256*16) {
            int r = i >> 4, o = i & 15;
            g_Wt5[i] = (o < 10) ? Wd4b[o*256 + r] : 0.f;
        }
    } else {
        int idx = (bid - 54) * 256 + threadIdx.x;
        if (idx >= NB*2*34*TT) return;
        int t = idx % TT;
        int r = idx / TT;
        int y = r % 34; r /= 34;
        int c = r % 2;
        int b = r / 2;
        const float* sp = s_in + ((size_t)((b*2 + c)*34 + y)*34)*TT + t;
        unsigned long long m = 0ull;
        for (int x = 0; x < 34; x++)
            if (sp[(size_t)x*TT] != 0.f) m |= (1ull << (x + 2));
        g_r0[((size_t)(t*NB + b)*2 + c)*34 + y] = m;
    }
}

// ---------------- coalesced smem-tiled transpose of Wd4a -> g_Wt4 ----------------
__global__ void prep_wt4(const float* __restrict__ Wd4a) {
    __shared__ float tile[32][33];
    int r0 = blockIdx.x * 32, o0 = blockIdx.y * 32;
    int tx = threadIdx.x, ty = threadIdx.y;              // 32 x 8
#pragma unroll
    for (int j = 0; j < 32; j += 8)
        tile[ty + j][tx] = Wd4a[(size_t)(o0 + ty + j)*2400 + r0 + tx];   // coalesced in r
    __syncthreads();
#pragma unroll
    for (int j = 0; j < 32; j += 8)
        g_Wt4[(size_t)(r0 + ty + j)*256 + o0 + tx] = tile[tx][ty + j];   // coalesced in o
}

// ---------------- conv1 acc (2->24, 5x5, pad2): warp per (t,b,x-pair) ----------------
__global__ void __launch_bounds__(256) conv1_acc() {
    int gw = blockIdx.x * 8 + (threadIdx.x >> 5);
    int lane = threadIdx.x & 31;
    if (gw >= TT*NB*578) return;
    int pr = gw % 578, tb = gw / 578;
    int y = pr / 17, x0 = (pr % 17) * 2;
    const unsigned long long* rt = g_r0 + (size_t)tb*68;
    float acc0 = 0.f, acc1 = 0.f;
#pragma unroll
    for (int ky = 0; ky < 5; ky++) {
        int yy = y + ky - 2;
        if (yy < 0 || yy >= 34) continue;
        unsigned long long ra = rt[yy], rb = rt[34 + yy];
        unsigned f0 = ((unsigned)(ra >> x0) & 31u) | (((unsigned)(rb >> x0) & 31u) << 5);
        unsigned f1 = ((unsigned)(ra >> (x0+1)) & 31u) | (((unsigned)(rb >> (x0+1)) & 31u) << 5);
        const float* wr = g_Wt1 + ky*320;
        while (f0) { int b = __ffs(f0) - 1; f0 &= f0 - 1; acc0 += wr[(b << 5) + lane]; }
        while (f1) { int b = __ffs(f1) - 1; f1 &= f1 - 1; acc1 += wr[(b << 5) + lane]; }
    }
    size_t base = ((size_t)tb*1156 + y*34 + x0)*32;
    g_A1[base + lane]      = acc0;
    g_A1[base + 32 + lane] = acc1;
}

// ---------------- pool1 + SRM fused: warp per (b,opix), uint2 loads, PF=8, rolling ptrs ----------------
__global__ void __launch_bounds__(512) pool1_srm() {
    int w = blockIdx.x * 16 + (threadIdx.x >> 5);
    int lane = threadIdx.x & 31;
    if (w >= NB*289) return;
    int b = w / 289, pix = w % 289;
    int y = pix / 17, x = pix % 17;
    int p0 = b*1156 + 2*y*34 + 2*x;                      // even -> uint2 aligned
    const int ST = 2312;                                 // uint2 per t-plane
    const uint2* mA = (const uint2*)g_M1 + (p0 >> 1);
    const uint2* mB = mA + 17;
    uint2 bufA[8], bufB[8];
#pragma unroll
    for (int k = 0; k < 8; k++) { bufA[k] = mA[k*ST]; bufB[k] = mB[k*ST]; }
    const uint2* pA = mA + 8*ST;
    const uint2* pB = mB + 8*ST;
    unsigned int* op = g_M2 + w;
    float p1 = 0, q1 = 0, p2 = 0, q2 = 0;
#pragma unroll 1
    for (int t0 = 0; t0 < 296; t0 += 8) {
#pragma unroll
        for (int k = 0; k < 8; k++) {
            uint2 a = bufA[k], c = bufB[k];
            bufA[k] = *pA; pA += ST;                     // padded planes
            bufB[k] = *pB; pB += ST;
            int cnt = ((a.x >> lane) & 1) + ((a.y >> lane) & 1)
                    + ((c.x >> lane) & 1) + ((c.y >> lane) & 1);
            float s = srm_step(p1, q1, p2, q2, 11.0f * (float)cnt);
            unsigned bal = __ballot_sync(0xffffffffu, s > 0.5f);
            if (!lane) *op = bal;
            op += NB*289;
        }
    }
#pragma unroll
    for (int k = 0; k < 4; k++) {                        // t = 296..299
        int cnt = ((bufA[k].x >> lane) & 1) + ((bufA[k].y >> lane) & 1)
                + ((bufB[k].x >> lane) & 1) + ((bufB[k].y >> lane) & 1);
        float s = srm_step(p1, q1, p2, q2, 11.0f * (float)cnt);
        unsigned bal = __ballot_sync(0xffffffffu, s > 0.5f);
        if (!lane) *op = bal;
        op += NB*289;
    }
}

// ---------------- conv2 acc (24->48, 3x3, pad1, 17x17): warp per (t,b,pixel) ----------------
__global__ void __launch_bounds__(256) conv2_acc() {
    int gw = blockIdx.x * 8 + (threadIdx.x >> 5);
    int lane = threadIdx.x & 31;
    if (gw >= TT*NB*289) return;
    int pix = gw % 289, tb = gw / 289;
    int y = pix / 17, x = pix % 17;
    const unsigned* mm = g_M2 + (size_t)tb*289;
    float aa = 0.f, ab = 0.f;
#pragma unroll
    for (int ky = 0; ky < 3; ky++) {
        int yy = y + ky - 1;
#pragma unroll
        for (int kx = 0; kx < 3; kx++) {
            int xx = x + kx - 1;
            unsigned m = 0u;
            if (yy >= 0 && yy < 17 && xx >= 0 && xx < 17) m = mm[yy*17 + xx];
            int kt = ky*3 + kx;
            while (m) {
                int c = __ffs(m) - 1; m &= m - 1;
                float2 wv = g_Wt2p[(c*9 + kt)*32 + lane];
                aa += wv.x; ab += wv.y;
            }
        }
    }
    g_A2[(size_t)gw*64 + lane]      = aa;
    g_A2[(size_t)gw*64 + lane + 32] = ab;
}

// ---------------- pool2 + SRM fused: warp per (b,opix,half), PF=8, rolling ptrs ----------------
__global__ void __launch_bounds__(512) pool2_srm() {
    int w = blockIdx.x * 16 + (threadIdx.x >> 5);
    int lane = threadIdx.x & 31;
    if (w >= NB*162) return;
    int b = w / 162, r = w % 162, pix = r >> 1, half = r & 1;
    int y = pix / 9, x = pix % 9;
    bool xv = (2*x + 1) < 17, yv = (2*y + 1) < 17;
    const int ST = 2312;                                 // words per t-plane
    const unsigned* m0 = g_M3 + b*578 + (2*y*17 + 2*x)*2 + half;
    const unsigned* m1 = m0 + 2;
    const unsigned* m2 = m0 + 34;
    const unsigned* m3 = m0 + 36;
    unsigned buf[8][4];
#pragma unroll
    for (int k = 0; k < 8; k++) {
        buf[k][0] = m0[k*ST];
        buf[k][1] = xv ? m1[k*ST] : 0u;
        buf[k][2] = yv ? m2[k*ST] : 0u;
        buf[k][3] = (xv && yv) ? m3[k*ST] : 0u;
    }
    const unsigned *p0 = m0 + 8*ST, *p1p = m1 + 8*ST, *p2p = m2 + 8*ST, *p3p = m3 + 8*ST;
    unsigned int* op = g_M4 + w;
    float p1 = 0, q1 = 0, p2 = 0, q2 = 0;
#pragma unroll 1
    for (int t0 = 0; t0 < 296; t0 += 8) {
#pragma unroll
        for (int k = 0; k < 8; k++) {
            int cnt = ((buf[k][0] >> lane) & 1) + ((buf[k][1] >> lane) & 1)
                    + ((buf[k][2] >> lane) & 1) + ((buf[k][3] >> lane) & 1);
            buf[k][0] = *p0; p0 += ST;
            buf[k][1] = xv ? *p1p : 0u; p1p += ST;
            buf[k][2] = yv ? *p2p : 0u; p2p += ST;
            buf[k][3] = (xv && yv) ? *p3p : 0u; p3p += ST;
            float s = srm_step(p1, q1, p2, q2, 11.0f * (float)cnt);
            unsigned bal = __ballot_sync(0xffffffffu, s > 0.5f);
            if (!lane) *op = bal;
            op += NB*162;
        }
    }
#pragma unroll
    for (int k = 0; k < 4; k++) {
        int cnt = ((buf[k][0] >> lane) & 1) + ((buf[k][1] >> lane) & 1)
                + ((buf[k][2] >> lane) & 1) + ((buf[k][3] >> lane) & 1);
        float s = srm_step(p1, q1, p2, q2, 11.0f * (float)cnt);
        unsigned bal = __ballot_sync(0xffffffffu, s > 0.5f);
        if (!lane) *op = bal;
        op += NB*162;
    }
}

// ---------------- conv3 acc (48->96, 3x3, pad1, 9x9): warp per (t,b,pixel), 3 outs/lane ----------------
__global__ void __launch_bounds__(256) conv3_acc() {
    int gw = blockIdx.x * 8 + (threadIdx.x >> 5);
    int lane = threadIdx.x & 31;
    if (gw >= TT*NB*81) return;
    int pix = gw % 81, tb = gw / 81;
    int y = pix / 9, x = pix % 9;
    const unsigned* mm = g_M4 + (size_t)tb*162;
    float a0 = 0.f, a1 = 0.f, a2 = 0.f;
#pragma unroll
    for (int ky = 0; ky < 3; ky++) {
        int yy = y + ky - 1;
#pragma unroll
        for (int kx = 0; kx < 3; kx++) {
            int xx = x + kx - 1;
            unsigned mlo = 0u, mhi = 0u;
            if (yy >= 0 && yy < 9 && xx >= 0 && xx < 9) {
                mlo = mm[(yy*9 + xx)*2];
                mhi = mm[(yy*9 + xx)*2 + 1];
            }
            int kt = ky*3 + kx;
            while (mlo) {
                int c = __ffs(mlo) - 1; mlo &= mlo - 1;
                float4 wv = g_Wt3p[(c*9 + kt)*32 + lane];
                a0 += wv.x; a1 += wv.y; a2 += wv.z;
            }
            while (mhi) {
                int c = __ffs(mhi) - 1; mhi &= mhi - 1;
                float4 wv = g_Wt3p[((c + 32)*9 + kt)*32 + lane];
                a0 += wv.x; a1 += wv.y; a2 += wv.z;
            }
        }
    }
    g_A3[(size_t)gw*96 + lane]      = a0;
    g_A3[(size_t)gw*96 + lane + 32] = a1;
    g_A3[(size_t)gw*96 + lane + 64] = a2;
}

// ---------------- pool3 + SRM fused: warp per (b,opix,wrd), PF=8, rolling ptrs ----------------
__global__ void __launch_bounds__(512) pool3_srm() {
    int w = blockIdx.x * 16 + (threadIdx.x >> 5);
    int lane = threadIdx.x & 31;
    if (w >= NB*75) return;
    int b = w / 75, r = w % 75, pix = r / 3, wrd = r % 3;
    int y = pix / 5, x = pix % 5;
    bool xv = (2*x + 1) < 9, yv = (2*y + 1) < 9;
    const int ST = 972;                                  // words per t-plane
    const unsigned* m0 = g_M5 + b*243 + (2*y*9 + 2*x)*3 + wrd;
    const unsigned* m1 = m0 + 3;
    const unsigned* m2 = m0 + 27;
    const unsigned* m3 = m0 + 30;
    unsigned buf[8][4];
#pragma unroll
    for (int k = 0; k < 8; k++) {
        buf[k][0] = m0[k*ST];
        buf[k][1] = xv ? m1[k*ST] : 0u;
        buf[k][2] = yv ? m2[k*ST] : 0u;
        buf[k][3] = (xv && yv) ? m3[k*ST] : 0u;
    }
    const unsigned *p0 = m0 + 8*ST, *p1p = m1 + 8*ST, *p2p = m2 + 8*ST, *p3p = m3 + 8*ST;
    unsigned int* op = g_M6 + w;
    float p1 = 0, q1 = 0, p2 = 0, q2 = 0;
#pragma unroll 1
    for (int t0 = 0; t0 < 296; t0 += 8) {
#pragma unroll
        for (int k = 0; k < 8; k++) {
            int cnt = ((buf[k][0] >> lane) & 1) + ((buf[k][1] >> lane) & 1)
                    + ((buf[k][2] >> lane) & 1) + ((buf[k][3] >> lane) & 1);
            buf[k][0] = *p0; p0 += ST;
            buf[k][1] = xv ? *p1p : 0u; p1p += ST;
            buf[k][2] = yv ? *p2p : 0u; p2p += ST;
            buf[k][3] = (xv && yv) ? *p3p : 0u; p3p += ST;
            float s = srm_step(p1, q1, p2, q2, 11.0f * (float)cnt);
            unsigned bal = __ballot_sync(0xffffffffu, s > 0.5f);
            if (!lane) *op = bal;
            op += NB*75;
        }
    }
#pragma unroll
    for (int k = 0; k < 4; k++) {
        int cnt = ((buf[k][0] >> lane) & 1) + ((buf[k][1] >> lane) & 1)
                + ((buf[k][2] >> lane) & 1) + ((buf[k][3] >> lane) & 1);
        float s = srm_step(p1, q1, p2, q2, 11.0f * (float)cnt);
        unsigned bal = __ballot_sync(0xffffffffu, s > 0.5f);
        if (!lane) *op = bal;
        op += NB*75;
    }
}

// ---------------- dense1 (2400->256): block per (t,b) ----------------
__global__ void __launch_bounds__(256) dense1() {
    int tb = blockIdx.x;
    int o = threadIdx.x;
    const unsigned* m = g_M6 + (size_t)tb*75;
    float acc = 0.f;
    for (int pos = 0; pos < 25; pos++)
        for (int wd = 0; wd < 3; wd++) {
            unsigned mm = m[pos*3 + wd];
            const float* wt = g_Wt4 + pos*256 + o;
            int cb = wd*32;
            while (mm) { int c = cb + __ffs(mm) - 1; mm &= mm - 1; acc += wt[(size_t)c*6400]; }
        }
    g_A7[(size_t)tb*256 + o] = acc;
}

// ---------------- dense2 (256->10): warp per (t,b), writes transposed ----------------
__global__ void __launch_bounds__(256) dense2() {
    int w = blockIdx.x * 8 + (threadIdx.x >> 5);
    int lane = threadIdx.x & 31;
    if (w >= TT*NB) return;
    int t = w / NB, b = w % NB;
    if (lane < 16) {
        const unsigned* m = g_M7 + (size_t)w*8;
        float acc = 0.f;
        for (int wd = 0; wd < 8; wd++) {
            unsigned mm = m[wd];
            int ib = wd*32;
            while (mm) { int i = ib + __ffs(mm) - 1; mm &= mm - 1; acc += g_Wt5[i*16 + lane]; }
        }
        g_A8T[(size_t)(b*16 + lane)*TT + t] = acc;
    }
}

// ---------------- final SRM -> output spikes (B,10,T) ----------------
__global__ void srm_out(float* __restrict__ out) {
    int tid = threadIdx.x;
    if (tid >= 40) return;
    int b = tid / 10, o = tid % 10;
    const float* ip = g_A8T + (size_t)(b*16 + o)*TT;
    const int PF = 8;
    float buf[PF];
#pragma unroll
    for (int k = 0; k < PF; k++) buf[k] = ip[k];
    float p1 = 0, q1 = 0, p2 = 0, q2 = 0;
    float* op = out + (size_t)(b*10 + o)*TT;
    for (int t0 = 0; t0 < TT; t0 += PF) {
#pragma unroll
        for (int k = 0; k < PF; k++) {
            int t = t0 + k;
            if (t >= TT) break;
            float x = buf[k];
            int tn = t + PF;
            buf[k] = (tn < TT) ? ip[tn] : 0.f;
            op[t] = srm_step(p1, q1, p2, q2, x);
        }
    }
}

extern "C" void kernel_launch(void* const* d_in, const int* in_sizes, int n_in,
                              void* d_out, int out_size) {
    const float* s_in = (const float*)d_in[0];
    const float* Wc1  = (const float*)d_in[1];
    const float* Wc2  = (const float*)d_in[2];
    const float* Wc3  = (const float*)d_in[3];
    const float* Wd4a = (const float*)d_in[4];
    const float* Wd4b = (const float*)d_in[5];
    float* out = (float*)d_out;

    init_all<<<54 + (NB*2*34*TT + 255)/256, 256>>>(Wc1, Wc2, Wc3, Wd4b, s_in);
    prep_wt4<<<dim3(75, 8), dim3(32, 8)>>>(Wd4a);

    conv1_acc<<<(TT*NB*578 + 7)/8, 256>>>();
    srm_scan_L1<<<(NB*1156 + 15)/16, 512>>>();
    pool1_srm<<<(NB*289 + 15)/16, 512>>>();

    conv2_acc<<<(TT*NB*289 + 7)/8, 256>>>();
    srm_scan_L2<<<(NB*289*2 + 15)/16, 512>>>();
    pool2_srm<<<(NB*162 + 15)/16, 512>>>();

    conv3_acc<<<(TT*NB*81 + 7)/8, 256>>>();
    srm_scan_L3<<<(NB*81*3 + 15)/16, 512>>>();
    pool3_srm<<<(NB*75 + 15)/16, 512>>>();

    dense1<<<TT*NB, 256>>>();
    srm_scan_D1<<<(NB*8 + 15)/16, 512>>>();

    dense2<<<(TT*NB + 7)/8, 256>>>();
    srm_out<<<1, 64>>>(out);
}

// round 8
// speedup vs baseline: 1.3065x; 1.0444x over previous
#include <cuda_runtime.h>

#define TT 300
#define NB 4

// ---------------- static device buffers (masks padded +8 planes for prefetch) ----------------
__device__ unsigned long long g_r0[TT*NB*2*34];                      // input row masks, bit (x+2)
__device__ __align__(16) unsigned int g_M1[(TT+8)*NB*1156];          // spikes L1: 24ch bits / pixel
__device__ unsigned int g_M2[TT*NB*289];                             // spikes P1
__device__ __align__(16) unsigned int g_M3[(TT+8)*NB*289*2];         // spikes L2: 48ch in 2 words
__device__ unsigned int g_M4[TT*NB*81*2];                            // spikes P2
__device__ __align__(16) unsigned int g_M5[(TT+8)*NB*81*3];          // spikes L3: 96ch in 3 words
__device__ unsigned int g_M6[TT*NB*25*3];                            // spikes P3
__device__ unsigned int g_M7[TT*NB*8];                               // spikes dense1: 256 bits

__device__ float g_A1[(size_t)TT*NB*1156*32];                        // conv1 pre-act (pad 24->32)
__device__ float g_A2[(size_t)TT*NB*289*64];                         // conv2 pre-act (pad 48->64)
__device__ float g_A3[(size_t)TT*NB*81*96];                          // conv3 pre-act
__device__ float g_A7[TT*NB*256];                                    // dense1 pre-act
__device__ float g_A8T[NB*16*TT];                                    // dense2 pre-act, [b][o][t]

__device__ float  g_Wt1[50*32];     // [(ky*10 + c*5+kx)][o pad32]
__device__ float2 g_Wt2p[216*32];   // [(c*9+kt)][lane] -> (o=lane, o=lane+32)
__device__ float4 g_Wt3p[432*32];   // [(c*9+kt)][lane] -> (o=lane, +32, +64, pad)
__device__ float  g_Wt4[2400*256];  // [(c*25+pos)][o 256]
__device__ float  g_Wt5[256*16];    // [i][o pad16]

// ---------------- SRM step: psp (tau=10) + spike w/ refractory (tau=1) ----------------
__device__ __forceinline__ float srm_step(float& p1, float& q1, float& p2, float& q2, float x) {
    const float A1 = 0.90483741803595952f;   // exp(-1/10)
    const float C1 = 0.27182818284590452f;   // e/10
    const float A2 = 0.36787944117144233f;   // exp(-1)
    const float C2 = 2.71828182845904523f;   // e
    const float RR = 20.0f * C2;             // SCALE_REF*THETA*c
    q1 = A1*q1 + A1*p1;
    p1 = A1*p1 + x;
    float y = C1 * q1;
    q2 = A2*q2 + A2*p2;
    float u = y - RR*q2;
    float s = (u >= 10.0f) ? 1.0f : 0.0f;
    p2 = A2*p2 + s;
    return s;
}

// ---------------- SRM scan: warp = 32 neurons, PF=12 rolling ring, 512-thr blocks ----------------
__device__ __forceinline__ void srm_scan_body(const float* __restrict__ in,
                                              unsigned int* __restrict__ out, int nW) {
    int w = blockIdx.x * 16 + (threadIdx.x >> 5);
    int lane = threadIdx.x & 31;
    if (w >= nW) return;
    size_t S = (size_t)nW * 32;
    const float* ip = in + (size_t)w*32 + lane;
    const int PF = 12;
    float buf[PF];
#pragma unroll
    for (int k = 0; k < PF; k++) buf[k] = ip[(size_t)k*S];
    const float* pf = ip + (size_t)PF*S;
    unsigned int* op = out + w;
    float p1=0,q1=0,p2=0,q2=0;
#pragma unroll 1
    for (int t0 = 0; t0 < TT - PF; t0 += PF) {          // 288 main steps
#pragma unroll
        for (int k = 0; k < PF; k++) {
            float x = buf[k];
            buf[k] = *pf; pf += S;                       // prefetch t+PF (max 299)
            float s = srm_step(p1, q1, p2, q2, x);
            unsigned bal = __ballot_sync(0xffffffffu, s > 0.5f);
            if (!lane) *op = bal;
            op += nW;
        }
    }
#pragma unroll
    for (int k = 0; k < PF; k++) {                       // t = 288..299
        float s = srm_step(p1, q1, p2, q2, buf[k]);
        unsigned bal = __ballot_sync(0xffffffffu, s > 0.5f);
        if (!lane) *op = bal;
        op += nW;
    }
}

__global__ void __launch_bounds__(512) srm_scan_L1() { srm_scan_body(g_A1, g_M1, NB*1156);  }
__global__ void __launch_bounds__(512) srm_scan_L2() { srm_scan_body(g_A2, g_M3, NB*289*2); }
__global__ void __launch_bounds__(512) srm_scan_L3() { srm_scan_body(g_A3, g_M5, NB*81*3);  }
__global__ void __launch_bounds__(512) srm_scan_D1() { srm_scan_body(g_A7, g_M7, NB*8);     }

// ---------------- init: small weight transposes ----------------
__global__ void init_weights(const float* __restrict__ Wc1, const float* __restrict__ Wc2,
                             const float* __restrict__ Wc3, const float* __restrict__ Wd4b) {
    int i = blockIdx.x * 256 + threadIdx.x;
    if (i < 50*32) {
        int tap = i >> 5, o = i & 31;
        int ky = tap / 10, bit = tap % 10, c = bit / 5, kx = bit % 5;
        g_Wt1[i] = (o < 24) ? Wc1[o*50 + c*25 + ky*5 + kx] : 0.f;
    }
    if (i < 216*32) {
        int tap = i >> 5, l = i & 31;
        float x = Wc2[l*216 + tap];
        float y = (l < 16) ? Wc2[(l + 32)*216 + tap] : 0.f;
        g_Wt2p[i] = make_float2(x, y);
    }
    if (i < 432*32) {
        int tap = i >> 5, l = i & 31;
        g_Wt3p[i] = make_float4(Wc3[l*432 + tap], Wc3[(l + 32)*432 + tap],
                                Wc3[(l + 64)*432 + tap], 0.f);
    }
    if (i < 256*16) {
        int r = i >> 4, o = i & 15;
        g_Wt5[i] = (o < 10) ? Wd4b[o*256 + r] : 0.f;
    }
}

// ---------------- pack s_in -> row bitmasks; warp=(b,c,y,t-chunk), lane=t: coalesced ----------------
__global__ void __launch_bounds__(512) pack_input(const float* __restrict__ s_in) {
    int w = blockIdx.x * 16 + (threadIdx.x >> 5);
    int lane = threadIdx.x & 31;
    if (w >= NB*2*34*10) return;
    int chunk = w % 10;
    int r = w / 10;
    int y = r % 34; r /= 34;
    int c = r % 2;
    int b = r / 2;
    int t = chunk * 32 + lane;
    bool tv = t < TT;
    const float* sp = s_in + ((size_t)((b*2 + c)*34 + y)*34)*TT + (tv ? t : 0);
    unsigned long long m = 0ull;
#pragma unroll
    for (int x = 0; x < 34; x++) {
        float v = sp[(size_t)x*TT];                      // lane-coalesced along t
        m |= (unsigned long long)(v != 0.f) << (x + 2);
    }
    if (tv) g_r0[((size_t)(t*NB + b)*2 + c)*34 + y] = m;
}

// ---------------- coalesced smem-tiled transpose of Wd4a -> g_Wt4 ----------------
__global__ void prep_wt4(const float* __restrict__ Wd4a) {
    __shared__ float tile[32][33];
    int r0 = blockIdx.x * 32, o0 = blockIdx.y * 32;
    int tx = threadIdx.x, ty = threadIdx.y;              // 32 x 8
#pragma unroll
    for (int j = 0; j < 32; j += 8)
        tile[ty + j][tx] = Wd4a[(size_t)(o0 + ty + j)*2400 + r0 + tx];   // coalesced in r
    __syncthreads();
#pragma unroll
    for (int j = 0; j < 32; j += 8)
        g_Wt4[(size_t)(r0 + ty + j)*256 + o0 + tx] = tile[tx][ty + j];   // coalesced in o
}

// ---------------- conv1 acc (2->24, 5x5, pad2): warp per (t,b,x-pair) ----------------
__global__ void __launch_bounds__(256) conv1_acc() {
    int gw = blockIdx.x * 8 + (threadIdx.x >> 5);
    int lane = threadIdx.x & 31;
    if (gw >= TT*NB*578) return;
    int pr = gw % 578, tb = gw / 578;
    int y = pr / 17, x0 = (pr % 17) * 2;
    const unsigned long long* rt = g_r0 + (size_t)tb*68;
    float acc0 = 0.f, acc1 = 0.f;
#pragma unroll
    for (int ky = 0; ky < 5; ky++) {
        int yy = y + ky - 2;
        if (yy < 0 || yy >= 34) continue;
        unsigned long long ra = rt[yy], rb = rt[34 + yy];
        unsigned f0 = ((unsigned)(ra >> x0) & 31u) | (((unsigned)(rb >> x0) & 31u) << 5);
        unsigned f1 = ((unsigned)(ra >> (x0+1)) & 31u) | (((unsigned)(rb >> (x0+1)) & 31u) << 5);
        const float* wr = g_Wt1 + ky*320;
        while (f0) { int b = __ffs(f0) - 1; f0 &= f0 - 1; acc0 += wr[(b << 5) + lane]; }
        while (f1) { int b = __ffs(f1) - 1; f1 &= f1 - 1; acc1 += wr[(b << 5) + lane]; }
    }
    size_t base = ((size_t)tb*1156 + y*34 + x0)*32;
    g_A1[base + lane]      = acc0;
    g_A1[base + 32 + lane] = acc1;
}

// ---------------- pool1 + SRM fused: warp per (b,opix), uint2 loads, PF=8, rolling ptrs ----------------
__global__ void __launch_bounds__(512) pool1_srm() {
    int w = blockIdx.x * 16 + (threadIdx.x >> 5);
    int lane = threadIdx.x & 31;
    if (w >= NB*289) return;
    int b = w / 289, pix = w % 289;
    int y = pix / 17, x = pix % 17;
    int p0 = b*1156 + 2*y*34 + 2*x;                      // even -> uint2 aligned
    const int ST = 2312;                                 // uint2 per t-plane
    const uint2* mA = (const uint2*)g_M1 + (p0 >> 1);
    const uint2* mB = mA + 17;
    uint2 bufA[8], bufB[8];
#pragma unroll
    for (int k = 0; k < 8; k++) { bufA[k] = mA[k*ST]; bufB[k] = mB[k*ST]; }
    const uint2* pA = mA + 8*ST;
    const uint2* pB = mB + 8*ST;
    unsigned int* op = g_M2 + w;
    float p1 = 0, q1 = 0, p2 = 0, q2 = 0;
#pragma unroll 1
    for (int t0 = 0; t0 < 296; t0 += 8) {
#pragma unroll
        for (int k = 0; k < 8; k++) {
            uint2 a = bufA[k], c = bufB[k];
            bufA[k] = *pA; pA += ST;                     // padded planes
            bufB[k] = *pB; pB += ST;
            int cnt = ((a.x >> lane) & 1) + ((a.y >> lane) & 1)
                    + ((c.x >> lane) & 1) + ((c.y >> lane) & 1);
            float s = srm_step(p1, q1, p2, q2, 11.0f * (float)cnt);
            unsigned bal = __ballot_sync(0xffffffffu, s > 0.5f);
            if (!lane) *op = bal;
            op += NB*289;
        }
    }
#pragma unroll
    for (int k = 0; k < 4; k++) {                        // t = 296..299
        int cnt = ((bufA[k].x >> lane) & 1) + ((bufA[k].y >> lane) & 1)
                + ((bufB[k].x >> lane) & 1) + ((bufB[k].y >> lane) & 1);
        float s = srm_step(p1, q1, p2, q2, 11.0f * (float)cnt);
        unsigned bal = __ballot_sync(0xffffffffu, s > 0.5f);
        if (!lane) *op = bal;
        op += NB*289;
    }
}

// ---------------- conv2 acc (24->48, 3x3, pad1, 17x17): warp per (t,b,x-PAIR), shared masks ----------------
__global__ void __launch_bounds__(256) conv2_acc() {
    int gw = blockIdx.x * 8 + (threadIdx.x >> 5);
    int lane = threadIdx.x & 31;
    if (gw >= TT*NB*153) return;                         // 17 rows x 9 pairs
    int pr = gw % 153, tb = gw / 153;
    int y = pr / 9, x0 = (pr % 9) * 2;
    bool x1v = (x0 + 1) < 17;
    const unsigned* mm = g_M2 + (size_t)tb*289;
    float aa0 = 0.f, ab0 = 0.f, aa1 = 0.f, ab1 = 0.f;
#pragma unroll
    for (int ky = 0; ky < 3; ky++) {
        int yy = y + ky - 1;
        if (yy < 0 || yy >= 17) continue;
        const unsigned* row = mm + yy*17;
#pragma unroll
        for (int xi = 0; xi < 4; xi++) {                 // input cols x0-1 .. x0+2
            int xx = x0 - 1 + xi;
            unsigned m = 0u;
            if (xx >= 0 && xx < 17 && (xi < 3 || x1v)) m = row[xx];
            while (m) {
                int c = __ffs(m) - 1; m &= m - 1;
                const float2* wb = g_Wt2p + c*288 + lane;     // c*9*32
                if (xi < 3) {                                 // pixel0: kt = ky*3+xi
                    float2 wv = wb[(ky*3 + xi)*32];
                    aa0 += wv.x; ab0 += wv.y;
                }
                if (xi >= 1 && x1v) {                         // pixel1: kt = ky*3+xi-1
                    float2 wv = wb[(ky*3 + xi - 1)*32];
                    aa1 += wv.x; ab1 += wv.y;
                }
            }
        }
    }
    size_t base = ((size_t)tb*289 + y*17 + x0)*64;
    g_A2[base + lane]      = aa0;
    g_A2[base + 32 + lane] = ab0;
    if (x1v) {
        g_A2[base + 64 + lane] = aa1;
        g_A2[base + 96 + lane] = ab1;
    }
}

// ---------------- pool2 + SRM fused: warp per (b,opix,half), PF=8, rolling ptrs ----------------
__global__ void __launch_bounds__(512) pool2_srm() {
    int w = blockIdx.x * 16 + (threadIdx.x >> 5);
    int lane = threadIdx.x & 31;
    if (w >= NB*162) return;
    int b = w / 162, r = w % 162, pix = r >> 1, half = r & 1;
    int y = pix / 9, x = pix % 9;
    bool xv = (2*x + 1) < 17, yv = (2*y + 1) < 17;
    const int ST = 2312;                                 // words per t-plane
    const unsigned* m0 = g_M3 + b*578 + (2*y*17 + 2*x)*2 + half;
    const unsigned* m1 = m0 + 2;
    const unsigned* m2 = m0 + 34;
    const unsigned* m3 = m0 + 36;
    unsigned buf[8][4];
#pragma unroll
    for (int k = 0; k < 8; k++) {
        buf[k][0] = m0[k*ST];
        buf[k][1] = xv ? m1[k*ST] : 0u;
        buf[k][2] = yv ? m2[k*ST] : 0u;
        buf[k][3] = (xv && yv) ? m3[k*ST] : 0u;
    }
    const unsigned *p0 = m0 + 8*ST, *p1p = m1 + 8*ST, *p2p = m2 + 8*ST, *p3p = m3 + 8*ST;
    unsigned int* op = g_M4 + w;
    float p1 = 0, q1 = 0, p2 = 0, q2 = 0;
#pragma unroll 1
    for (int t0 = 0; t0 < 296; t0 += 8) {
#pragma unroll
        for (int k = 0; k < 8; k++) {
            int cnt = ((buf[k][0] >> lane) & 1) + ((buf[k][1] >> lane) & 1)
                    + ((buf[k][2] >> lane) & 1) + ((buf[k][3] >> lane) & 1);
            buf[k][0] = *p0; p0 += ST;
            buf[k][1] = xv ? *p1p : 0u; p1p += ST;
            buf[k][2] = yv ? *p2p : 0u; p2p += ST;
            buf[k][3] = (xv && yv) ? *p3p : 0u; p3p += ST;
            float s = srm_step(p1, q1, p2, q2, 11.0f * (float)cnt);
            unsigned bal = __ballot_sync(0xffffffffu, s > 0.5f);
            if (!lane) *op = bal;
            op += NB*162;
        }
    }
#pragma unroll
    for (int k = 0; k < 4; k++) {
        int cnt = ((buf[k][0] >> lane) & 1) + ((buf[k][1] >> lane) & 1)
                + ((buf[k][2] >> lane) & 1) + ((buf[k][3] >> lane) & 1);
        float s = srm_step(p1, q1, p2, q2, 11.0f * (float)cnt);
        unsigned bal = __ballot_sync(0xffffffffu, s > 0.5f);
        if (!lane) *op = bal;
        op += NB*162;
    }
}

// ---------------- conv3 acc (48->96, 3x3, pad1, 9x9): warp per (t,b,x-PAIR), shared masks ----------------
__global__ void __launch_bounds__(256) conv3_acc() {
    int gw = blockIdx.x * 8 + (threadIdx.x >> 5);
    int lane = threadIdx.x & 31;
    if (gw >= TT*NB*45) return;                          // 9 rows x 5 pairs
    int pr = gw % 45, tb = gw / 45;
    int y = pr / 5, x0 = (pr % 5) * 2;
    bool x1v = (x0 + 1) < 9;
    const unsigned* mm = g_M4 + (size_t)tb*162;
    float a00 = 0.f, a01 = 0.f, a02 = 0.f;
    float a10 = 0.f, a11 = 0.f, a12 = 0.f;
#pragma unroll
    for (int ky = 0; ky < 3; ky++) {
        int yy = y + ky - 1;
        if (yy < 0 || yy >= 9) continue;
        const unsigned* row = mm + yy*18;
#pragma unroll
        for (int xi = 0; xi < 4; xi++) {                 // input cols x0-1 .. x0+2
            int xx = x0 - 1 + xi;
            unsigned mlo = 0u, mhi = 0u;
            if (xx >= 0 && xx < 9 && (xi < 3 || x1v)) {
                mlo = row[xx*2];
                mhi = row[xx*2 + 1];
            }
            while (mlo) {
                int c = __ffs(mlo) - 1; mlo &= mlo - 1;
                const float4* wb = g_Wt3p + c*288 + lane;
                if (xi < 3) {
                    float4 wv = wb[(ky*3 + xi)*32];
                    a00 += wv.x; a01 += wv.y; a02 += wv.z;
                }
                if (xi >= 1 && x1v) {
                    float4 wv = wb[(ky*3 + xi - 1)*32];
                    a10 += wv.x; a11 += wv.y; a12 += wv.z;
                }
            }
            while (mhi) {
                int c = __ffs(mhi) - 1; mhi &= mhi - 1;
                const float4* wb = g_Wt3p + (c + 32)*288 + lane;
                if (xi < 3) {
                    float4 wv = wb[(ky*3 + xi)*32];
                    a00 += wv.x; a01 += wv.y; a02 += wv.z;
                }
                if (xi >= 1 && x1v) {
                    float4 wv = wb[(ky*3 + xi - 1)*32];
                    a10 += wv.x; a11 += wv.y; a12 += wv.z;
                }
            }
        }
    }
    size_t base = ((size_t)tb*81 + y*9 + x0)*96;
    g_A3[base + lane]      = a00;
    g_A3[base + 32 + lane] = a01;
    g_A3[base + 64 + lane] = a02;
    if (x1v) {
        g_A3[base + 96 + lane]  = a10;
        g_A3[base + 128 + lane] = a11;
        g_A3[base + 160 + lane] = a12;
    }
}

// ---------------- pool3 + SRM fused: warp per (b,opix,wrd), PF=8, rolling ptrs ----------------
__global__ void __launch_bounds__(512) pool3_srm() {
    int w = blockIdx.x * 16 + (threadIdx.x >> 5);
    int lane = threadIdx.x & 31;
    if (w >= NB*75) return;
    int b = w / 75, r = w % 75, pix = r / 3, wrd = r % 3;
    int y = pix / 5, x = pix % 5;
    bool xv = (2*x + 1) < 9, yv = (2*y + 1) < 9;
    const int ST = 972;                                  // words per t-plane
    const unsigned* m0 = g_M5 + b*243 + (2*y*9 + 2*x)*3 + wrd;
    const unsigned* m1 = m0 + 3;
    const unsigned* m2 = m0 + 27;
    const unsigned* m3 = m0 + 30;
    unsigned buf[8][4];
#pragma unroll
    for (int k = 0; k < 8; k++) {
        buf[k][0] = m0[k*ST];
        buf[k][1] = xv ? m1[k*ST] : 0u;
        buf[k][2] = yv ? m2[k*ST] : 0u;
        buf[k][3] = (xv && yv) ? m3[k*ST] : 0u;
    }
    const unsigned *p0 = m0 + 8*ST, *p1p = m1 + 8*ST, *p2p = m2 + 8*ST, *p3p = m3 + 8*ST;
    unsigned int* op = g_M6 + w;
    float p1 = 0, q1 = 0, p2 = 0, q2 = 0;
#pragma unroll 1
    for (int t0 = 0; t0 < 296; t0 += 8) {
#pragma unroll
        for (int k = 0; k < 8; k++) {
            int cnt = ((buf[k][0] >> lane) & 1) + ((buf[k][1] >> lane) & 1)
                    + ((buf[k][2] >> lane) & 1) + ((buf[k][3] >> lane) & 1);
            buf[k][0] = *p0; p0 += ST;
            buf[k][1] = xv ? *p1p : 0u; p1p += ST;
            buf[k][2] = yv ? *p2p : 0u; p2p += ST;
            buf[k][3] = (xv && yv) ? *p3p : 0u; p3p += ST;
            float s = srm_step(p1, q1, p2, q2, 11.0f * (float)cnt);
            unsigned bal = __ballot_sync(0xffffffffu, s > 0.5f);
            if (!lane) *op = bal;
            op += NB*75;
        }
    }
#pragma unroll
    for (int k = 0; k < 4; k++) {
        int cnt = ((buf[k][0] >> lane) & 1) + ((buf[k][1] >> lane) & 1)
                + ((buf[k][2] >> lane) & 1) + ((buf[k][3] >> lane) & 1);
        float s = srm_step(p1, q1, p2, q2, 11.0f * (float)cnt);
        unsigned bal = __ballot_sync(0xffffffffu, s > 0.5f);
        if (!lane) *op = bal;
        op += NB*75;
    }
}

// ---------------- dense1 (2400->256): block per (t,b) ----------------
__global__ void __launch_bounds__(256) dense1() {
    int tb = blockIdx.x;
    int o = threadIdx.x;
    const unsigned* m = g_M6 + (size_t)tb*75;
    float acc = 0.f;
    for (int pos = 0; pos < 25; pos++)
        for (int wd = 0; wd < 3; wd++) {
            unsigned mm = m[pos*3 + wd];
            const float* wt = g_Wt4 + pos*256 + o;
            int cb = wd*32;
            while (mm) { int c = cb + __ffs(mm) - 1; mm &= mm - 1; acc += wt[(size_t)c*6400]; }
        }
    g_A7[(size_t)tb*256 + o] = acc;
}

// ---------------- dense2 (256->10): warp per (t,b), writes transposed ----------------
__global__ void __launch_bounds__(256) dense2() {
    int w = blockIdx.x * 8 + (threadIdx.x >> 5);
    int lane = threadIdx.x & 31;
    if (w >= TT*NB) return;
    int t = w / NB, b = w % NB;
    if (lane < 16) {
        const unsigned* m = g_M7 + (size_t)w*8;
        float acc = 0.f;
        for (int wd = 0; wd < 8; wd++) {
            unsigned mm = m[wd];
            int ib = wd*32;
            while (mm) { int i = ib + __ffs(mm) - 1; mm &= mm - 1; acc += g_Wt5[i*16 + lane]; }
        }
        g_A8T[(size_t)(b*16 + lane)*TT + t] = acc;
    }
}

// ---------------- final SRM -> output spikes (B,10,T) ----------------
__global__ void srm_out(float* __restrict__ out) {
    int tid = threadIdx.x;
    if (tid >= 40) return;
    int b = tid / 10, o = tid % 10;
    const float* ip = g_A8T + (size_t)(b*16 + o)*TT;
    const int PF = 8;
    float buf[PF];
#pragma unroll
    for (int k = 0; k < PF; k++) buf[k] = ip[k];
    float p1 = 0, q1 = 0, p2 = 0, q2 = 0;
    float* op = out + (size_t)(b*10 + o)*TT;
    for (int t0 = 0; t0 < TT; t0 += PF) {
#pragma unroll
        for (int k = 0; k < PF; k++) {
            int t = t0 + k;
            if (t >= TT) break;
            float x = buf[k];
            int tn = t + PF;
            buf[k] = (tn < TT) ? ip[tn] : 0.f;
            op[t] = srm_step(p1, q1, p2, q2, x);
        }
    }
}

extern "C" void kernel_launch(void* const* d_in, const int* in_sizes, int n_in,
                              void* d_out, int out_size) {
    const float* s_in = (const float*)d_in[0];
    const float* Wc1  = (const float*)d_in[1];
    const float* Wc2  = (const float*)d_in[2];
    const float* Wc3  = (const float*)d_in[3];
    const float* Wd4a = (const float*)d_in[4];
    const float* Wd4b = (const float*)d_in[5];
    float* out = (float*)d_out;

    // slots 0..2 so conv1_acc lands in the profiled 4th slot
    init_weights<<<54, 256>>>(Wc1, Wc2, Wc3, Wd4b);
    pack_input<<<(NB*2*34*10 + 15)/16, 512>>>(s_in);
    prep_wt4<<<dim3(75, 8), dim3(32, 8)>>>(Wd4a);

    conv1_acc<<<(TT*NB*578 + 7)/8, 256>>>();
    srm_scan_L1<<<(NB*1156 + 15)/16, 512>>>();
    pool1_srm<<<(NB*289 + 15)/16, 512>>>();

    conv2_acc<<<(TT*NB*153 + 7)/8, 256>>>();
    srm_scan_L2<<<(NB*289*2 + 15)/16, 512>>>();
    pool2_srm<<<(NB*162 + 15)/16, 512>>>();

    conv3_acc<<<(TT*NB*45 + 7)/8, 256>>>();
    srm_scan_L3<<<(NB*81*3 + 15)/16, 512>>>();
    pool3_srm<<<(NB*75 + 15)/16, 512>>>();

    dense1<<<TT*NB, 256>>>();
    srm_scan_D1<<<1, 512>>>();

    dense2<<<(TT*NB + 7)/8, 256>>>();
    srm_out<<<1, 64>>>(out);
}

// round 10
// speedup vs baseline: 1.3602x; 1.0411x over previous
#include <cuda_runtime.h>

#define TT 300
#define NB 4

// ---------------- static device buffers (masks padded +8 planes for prefetch) ----------------
__device__ unsigned long long g_r0[TT*NB*2*34];                      // input row masks, bit (x+2)
__device__ __align__(16) unsigned int g_M1[(TT+8)*NB*1156];          // spikes L1: 24ch bits / pixel
__device__ unsigned int g_M2[TT*NB*289];                             // spikes P1
__device__ __align__(16) unsigned int g_M3[(TT+8)*NB*289*2];         // spikes L2: 48ch in 2 words
__device__ unsigned int g_M4[TT*NB*81*2];                            // spikes P2
__device__ __align__(16) unsigned int g_M5[(TT+8)*NB*81*3];          // spikes L3: 96ch in 3 words
__device__ unsigned int g_M6[TT*NB*25*3];                            // spikes P3
__device__ unsigned int g_M7[TT*NB*8];                               // spikes dense1: 256 bits

__device__ float g_A1[(size_t)TT*NB*1156*32];                        // conv1 pre-act (pad 24->32)
__device__ float g_A2[(size_t)TT*NB*289*64];                         // conv2 pre-act (pad 48->64)
__device__ float g_A3[(size_t)TT*NB*81*96];                          // conv3 pre-act
__device__ __align__(16) float g_A7[TT*NB*256];                      // dense1 pre-act
__device__ float g_A8T[NB*16*TT];                                    // dense2 pre-act, [b][o][t]

__device__ float  g_Wt1[50*32];     // [(ky*10 + c*5+kx)][o pad32]
__device__ float2 g_Wt2p[216*32];   // [(c*9+kt)][lane] -> (o=lane, o=lane+32)
__device__ float4 g_Wt3p[432*32];   // [(c*9+kt)][lane] -> (o=lane, +32, +64, pad)
__device__ __align__(16) float g_Wt4[2400*256];  // [(c*25+pos)][o 256]
__device__ float  g_Wt5[256*16];    // [i][o pad16]

// ---------------- SRM step: psp (tau=10) + spike w/ refractory (tau=1) ----------------
__device__ __forceinline__ float srm_step(float& p1, float& q1, float& p2, float& q2, float x) {
    const float A1 = 0.90483741803595952f;   // exp(-1/10)
    const float C1 = 0.27182818284590452f;   // e/10
    const float A2 = 0.36787944117144233f;   // exp(-1)
    const float C2 = 2.71828182845904523f;   // e
    const float RR = 20.0f * C2;             // SCALE_REF*THETA*c
    q1 = A1*q1 + A1*p1;
    p1 = A1*p1 + x;
    float y = C1 * q1;
    q2 = A2*q2 + A2*p2;
    float u = y - RR*q2;
    float s = (u >= 10.0f) ? 1.0f : 0.0f;
    p2 = A2*p2 + s;
    return s;
}

// ---------------- SRM scan: warp = 32 neurons, PF=12 rolling ring, 512-thr blocks ----------------
__device__ __forceinline__ void srm_scan_body(const float* __restrict__ in,
                                              unsigned int* __restrict__ out, int nW) {
    int w = blockIdx.x * 16 + (threadIdx.x >> 5);
    int lane = threadIdx.x & 31;
    if (w >= nW) return;
    size_t S = (size_t)nW * 32;
    const float* ip = in + (size_t)w*32 + lane;
    const int PF = 12;
    float buf[PF];
#pragma unroll
    for (int k = 0; k < PF; k++) buf[k] = ip[(size_t)k*S];
    const float* pf = ip + (size_t)PF*S;
    unsigned int* op = out + w;
    float p1=0,q1=0,p2=0,q2=0;
#pragma unroll 1
    for (int t0 = 0; t0 < TT - PF; t0 += PF) {          // 288 main steps
#pragma unroll
        for (int k = 0; k < PF; k++) {
            float x = buf[k];
            buf[k] = *pf; pf += S;                       // prefetch t+PF (max 299)
            float s = srm_step(p1, q1, p2, q2, x);
            unsigned bal = __ballot_sync(0xffffffffu, s > 0.5f);
            if (!lane) *op = bal;
            op += nW;
        }
    }
#pragma unroll
    for (int k = 0; k < PF; k++) {                       // t = 288..299
        float s = srm_step(p1, q1, p2, q2, buf[k]);
        unsigned bal = __ballot_sync(0xffffffffu, s > 0.5f);
        if (!lane) *op = bal;
        op += nW;
    }
}

__global__ void __launch_bounds__(512) srm_scan_L1() { srm_scan_body(g_A1, g_M1, NB*1156);  }
__global__ void __launch_bounds__(512) srm_scan_L2() { srm_scan_body(g_A2, g_M3, NB*289*2); }
__global__ void __launch_bounds__(512) srm_scan_L3() { srm_scan_body(g_A3, g_M5, NB*81*3);  }
__global__ void __launch_bounds__(512) srm_scan_D1() { srm_scan_body(g_A7, g_M7, NB*8);     }

// ---------------- init: small weight transposes ----------------
__global__ void init_weights(const float* __restrict__ Wc1, const float* __restrict__ Wc2,
                             const float* __restrict__ Wc3, const float* __restrict__ Wd4b) {
    int i = blockIdx.x * 256 + threadIdx.x;
    if (i < 50*32) {
        int tap = i >> 5, o = i & 31;
        int ky = tap / 10, bit = tap % 10, c = bit / 5, kx = bit % 5;
        g_Wt1[i] = (o < 24) ? Wc1[o*50 + c*25 + ky*5 + kx] : 0.f;
    }
    if (i < 216*32) {
        int tap = i >> 5, l = i & 31;
        float x = Wc2[l*216 + tap];
        float y = (l < 16) ? Wc2[(l + 32)*216 + tap] : 0.f;
        g_Wt2p[i] = make_float2(x, y);
    }
    if (i < 432*32) {
        int tap = i >> 5, l = i & 31;
        g_Wt3p[i] = make_float4(Wc3[l*432 + tap], Wc3[(l + 32)*432 + tap],
                                Wc3[(l + 64)*432 + tap], 0.f);
    }
    if (i < 256*16) {
        int r = i >> 4, o = i & 15;
        g_Wt5[i] = (o < 10) ? Wd4b[o*256 + r] : 0.f;
    }
}

// ---------------- pack s_in -> row bitmasks; warp=(b,c,y,t-chunk), lane=t: coalesced ----------------
__global__ void __launch_bounds__(512) pack_input(const float* __restrict__ s_in) {
    int w = blockIdx.x * 16 + (threadIdx.x >> 5);
    int lane = threadIdx.x & 31;
    if (w >= NB*2*34*10) return;
    int chunk = w % 10;
    int r = w / 10;
    int y = r % 34; r /= 34;
    int c = r % 2;
    int b = r / 2;
    int t = chunk * 32 + lane;
    bool tv = t < TT;
    const float* sp = s_in + ((size_t)((b*2 + c)*34 + y)*34)*TT + (tv ? t : 0);
    unsigned long long m = 0ull;
#pragma unroll
    for (int x = 0; x < 34; x++) {
        float v = sp[(size_t)x*TT];                      // lane-coalesced along t
        m |= (unsigned long long)(v != 0.f) << (x + 2);
    }
    if (tv) g_r0[((size_t)(t*NB + b)*2 + c)*34 + y] = m;
}

// ---------------- coalesced smem-tiled transpose of Wd4a -> g_Wt4 ----------------
__global__ void prep_wt4(const float* __restrict__ Wd4a) {
    __shared__ float tile[32][33];
    int r0 = blockIdx.x * 32, o0 = blockIdx.y * 32;
    int tx = threadIdx.x, ty = threadIdx.y;              // 32 x 8
#pragma unroll
    for (int j = 0; j < 32; j += 8)
        tile[ty + j][tx] = Wd4a[(size_t)(o0 + ty + j)*2400 + r0 + tx];   // coalesced in r
    __syncthreads();
#pragma unroll
    for (int j = 0; j < 32; j += 8)
        g_Wt4[(size_t)(r0 + ty + j)*256 + o0 + tx] = tile[tx][ty + j];   // coalesced in o
}

// ---------------- conv1 acc (2->24, 5x5, pad2): warp per (t,b,x-QUAD), event-direct ----------------
__global__ void __launch_bounds__(256) conv1_acc() {
    int gw = blockIdx.x * 8 + (threadIdx.x >> 5);
    int lane = threadIdx.x & 31;
    if (gw >= TT*NB*306) return;                         // 34 rows x 9 quads
    int pr = gw % 306, tb = gw / 306;
    int y = pr / 9, x0 = (pr % 9) * 4;
    const unsigned long long* rt = g_r0 + (size_t)tb*68;
    float a0 = 0.f, a1 = 0.f, a2 = 0.f, a3 = 0.f;
#pragma unroll
    for (int ky = 0; ky < 5; ky++) {
        int yy = y + ky - 2;
        if (yy < 0 || yy >= 34) continue;
        unsigned w0 = (unsigned)(rt[yy] >> x0) & 0xFFu;        // taps for pixels x0..x0+3, c=0
        unsigned w1 = (unsigned)(rt[34 + yy] >> x0) & 0xFFu;   // c=1
        unsigned f = w0 | (w1 << 8);
        if (!f) continue;                                // early-out: common at 3% density
        const float* wk = g_Wt1 + ky*320 + lane;
        do {
            int bit = __ffs(f) - 1; f &= f - 1;
            int c = bit >> 3, j = bit & 7;               // j = input col - x0
            const float* wr = wk + c*160;                // + (c*5)*32
            if (j <= 4)           a0 += wr[j*32];        // kx = j - p
            if (j >= 1 && j <= 5) a1 += wr[(j - 1)*32];
            if (j >= 2 && j <= 6) a2 += wr[(j - 2)*32];
            if (j >= 3)           a3 += wr[(j - 3)*32];
        } while (f);
    }
    size_t base = ((size_t)tb*1156 + y*34 + x0)*32;
    g_A1[base + lane]      = a0;
    g_A1[base + 32 + lane] = a1;
    if (x0 + 2 < 34) {                                   // last quad has only 2 valid pixels
        g_A1[base + 64 + lane] = a2;
        g_A1[base + 96 + lane] = a3;
    }
}

// ---------------- pool1 + SRM fused: warp per (b,opix), uint2 loads, PF=8, rolling ptrs ----------------
__global__ void __launch_bounds__(512) pool1_srm() {
    int w = blockIdx.x * 16 + (threadIdx.x >> 5);
    int lane = threadIdx.x & 31;
    if (w >= NB*289) return;
    int b = w / 289, pix = w % 289;
    int y = pix / 17, x = pix % 17;
    int p0 = b*1156 + 2*y*34 + 2*x;                      // even -> uint2 aligned
    const int ST = 2312;                                 // uint2 per t-plane
    const uint2* mA = (const uint2*)g_M1 + (p0 >> 1);
    const uint2* mB = mA + 17;
    uint2 bufA[8], bufB[8];
#pragma unroll
    for (int k = 0; k < 8; k++) { bufA[k] = mA[k*ST]; bufB[k] = mB[k*ST]; }
    const uint2* pA = mA + 8*ST;
    const uint2* pB = mB + 8*ST;
    unsigned int* op = g_M2 + w;
    float p1 = 0, q1 = 0, p2 = 0, q2 = 0;
#pragma unroll 1
    for (int t0 = 0; t0 < 296; t0 += 8) {
#pragma unroll
        for (int k = 0; k < 8; k++) {
            uint2 a = bufA[k], c = bufB[k];
            bufA[k] = *pA; pA += ST;                     // padded planes
            bufB[k] = *pB; pB += ST;
            int cnt = ((a.x >> lane) & 1) + ((a.y >> lane) & 1)
                    + ((c.x >> lane) & 1) + ((c.y >> lane) & 1);
            float s = srm_step(p1, q1, p2, q2, 11.0f * (float)cnt);
            unsigned bal = __ballot_sync(0xffffffffu, s > 0.5f);
            if (!lane) *op = bal;
            op += NB*289;
        }
    }
#pragma unroll
    for (int k = 0; k < 4; k++) {                        // t = 296..299
        int cnt = ((bufA[k].x >> lane) & 1) + ((bufA[k].y >> lane) & 1)
                + ((bufB[k].x >> lane) & 1) + ((bufB[k].y >> lane) & 1);
        float s = srm_step(p1, q1, p2, q2, 11.0f * (float)cnt);
        unsigned bal = __ballot_sync(0xffffffffu, s > 0.5f);
        if (!lane) *op = bal;
        op += NB*289;
    }
}

// ---------------- conv2 acc (24->48, 3x3, pad1, 17x17): warp per (t,b,x-PAIR), shared masks ----------------
__global__ void __launch_bounds__(256) conv2_acc() {
    int gw = blockIdx.x * 8 + (threadIdx.x >> 5);
    int lane = threadIdx.x & 31;
    if (gw >= TT*NB*153) return;                         // 17 rows x 9 pairs
    int pr = gw % 153, tb = gw / 153;
    int y = pr / 9, x0 = (pr % 9) * 2;
    bool x1v = (x0 + 1) < 17;
    const unsigned* mm = g_M2 + (size_t)tb*289;
    float aa0 = 0.f, ab0 = 0.f, aa1 = 0.f, ab1 = 0.f;
#pragma unroll
    for (int ky = 0; ky < 3; ky++) {
        int yy = y + ky - 1;
        if (yy < 0 || yy >= 17) continue;
        const unsigned* row = mm + yy*17;
#pragma unroll
        for (int xi = 0; xi < 4; xi++) {                 // input cols x0-1 .. x0+2
            int xx = x0 - 1 + xi;
            unsigned m = 0u;
            if (xx >= 0 && xx < 17 && (xi < 3 || x1v)) m = row[xx];
            while (m) {
                int c = __ffs(m) - 1; m &= m - 1;
                const float2* wb = g_Wt2p + c*288 + lane;     // c*9*32
                if (xi < 3) {                                 // pixel0: kt = ky*3+xi
                    float2 wv = wb[(ky*3 + xi)*32];
                    aa0 += wv.x; ab0 += wv.y;
                }
                if (xi >= 1 && x1v) {                         // pixel1: kt = ky*3+xi-1
                    float2 wv = wb[(ky*3 + xi - 1)*32];
                    aa1 += wv.x; ab1 += wv.y;
                }
            }
        }
    }
    size_t base = ((size_t)tb*289 + y*17 + x0)*64;
    g_A2[base + lane]      = aa0;
    g_A2[base + 32 + lane] = ab0;
    if (x1v) {
        g_A2[base + 64 + lane] = aa1;
        g_A2[base + 96 + lane] = ab1;
    }
}

// ---------------- pool2 + SRM fused: warp per (b,opix,half), PF=8, rolling ptrs ----------------
__global__ void __launch_bounds__(512) pool2_srm() {
    int w = blockIdx.x * 16 + (threadIdx.x >> 5);
    int lane = threadIdx.x & 31;
    if (w >= NB*162) return;
    int b = w / 162, r = w % 162, pix = r >> 1, half = r & 1;
    int y = pix / 9, x = pix % 9;
    bool xv = (2*x + 1) < 17, yv = (2*y + 1) < 17;
    const int ST = 2312;                                 // words per t-plane
    const unsigned* m0 = g_M3 + b*578 + (2*y*17 + 2*x)*2 + half;
    const unsigned* m1 = m0 + 2;
    const unsigned* m2 = m0 + 34;
    const unsigned* m3 = m0 + 36;
    unsigned buf[8][4];
#pragma unroll
    for (int k = 0; k < 8; k++) {
        buf[k][0] = m0[k*ST];
        buf[k][1] = xv ? m1[k*ST] : 0u;
        buf[k][2] = yv ? m2[k*ST] : 0u;
        buf[k][3] = (xv && yv) ? m3[k*ST] : 0u;
    }
    const unsigned *p0 = m0 + 8*ST, *p1p = m1 + 8*ST, *p2p = m2 + 8*ST, *p3p = m3 + 8*ST;
    unsigned int* op = g_M4 + w;
    float p1 = 0, q1 = 0, p2 = 0, q2 = 0;
#pragma unroll 1
    for (int t0 = 0; t0 < 296; t0 += 8) {
#pragma unroll
        for (int k = 0; k < 8; k++) {
            int cnt = ((buf[k][0] >> lane) & 1) + ((buf[k][1] >> lane) & 1)
                    + ((buf[k][2] >> lane) & 1) + ((buf[k][3] >> lane) & 1);
            buf[k][0] = *p0; p0 += ST;
            buf[k][1] = xv ? *p1p : 0u; p1p += ST;
            buf[k][2] = yv ? *p2p : 0u; p2p += ST;
            buf[k][3] = (xv && yv) ? *p3p : 0u; p3p += ST;
            float s = srm_step(p1, q1, p2, q2, 11.0f * (float)cnt);
            unsigned bal = __ballot_sync(0xffffffffu, s > 0.5f);
            if (!lane) *op = bal;
            op += NB*162;
        }
    }
#pragma unroll
    for (int k = 0; k < 4; k++) {
        int cnt = ((buf[k][0] >> lane) & 1) + ((buf[k][1] >> lane) & 1)
                + ((buf[k][2] >> lane) & 1) + ((buf[k][3] >> lane) & 1);
        float s = srm_step(p1, q1, p2, q2, 11.0f * (float)cnt);
        unsigned bal = __ballot_sync(0xffffffffu, s > 0.5f);
        if (!lane) *op = bal;
        op += NB*162;
    }
}

// ---------------- conv3 acc (48->96, 3x3, pad1, 9x9): warp per (t,b,x-PAIR), shared masks ----------------
__global__ void __launch_bounds__(256) conv3_acc() {
    int gw = blockIdx.x * 8 + (threadIdx.x >> 5);
    int lane = threadIdx.x & 31;
    if (gw >= TT*NB*45) return;                          // 9 rows x 5 pairs
    int pr = gw % 45, tb = gw / 45;
    int y = pr / 5, x0 = (pr % 5) * 2;
    bool x1v = (x0 + 1) < 9;
    const unsigned* mm = g_M4 + (size_t)tb*162;
    float a00 = 0.f, a01 = 0.f, a02 = 0.f;
    float a10 = 0.f, a11 = 0.f, a12 = 0.f;
#pragma unroll
    for (int ky = 0; ky < 3; ky++) {
        int yy = y + ky - 1;
        if (yy < 0 || yy >= 9) continue;
        const unsigned* row = mm + yy*18;
#pragma unroll
        for (int xi = 0; xi < 4; xi++) {                 // input cols x0-1 .. x0+2
            int xx = x0 - 1 + xi;
            unsigned mlo = 0u, mhi = 0u;
            if (xx >= 0 && xx < 9 && (xi < 3 || x1v)) {
                mlo = row[xx*2];
                mhi = row[xx*2 + 1];
            }
            while (mlo) {
                int c = __ffs(mlo) - 1; mlo &= mlo - 1;
                const float4* wb = g_Wt3p + c*288 + lane;
                if (xi < 3) {
                    float4 wv = wb[(ky*3 + xi)*32];
                    a00 += wv.x; a01 += wv.y; a02 += wv.z;
                }
                if (xi >= 1 && x1v) {
                    float4 wv = wb[(ky*3 + xi - 1)*32];
                    a10 += wv.x; a11 += wv.y; a12 += wv.z;
                }
            }
            while (mhi) {
                int c = __ffs(mhi) - 1; mhi &= mhi - 1;
                const float4* wb = g_Wt3p + (c + 32)*288 + lane;
                if (xi < 3) {
                    float4 wv = wb[(ky*3 + xi)*32];
                    a00 += wv.x; a01 += wv.y; a02 += wv.z;
                }
                if (xi >= 1 && x1v) {
                    float4 wv = wb[(ky*3 + xi - 1)*32];
                    a10 += wv.x; a11 += wv.y; a12 += wv.z;
                }
            }
        }
    }
    size_t base = ((size_t)tb*81 + y*9 + x0)*96;
    g_A3[base + lane]      = a00;
    g_A3[base + 32 + lane] = a01;
    g_A3[base + 64 + lane] = a02;
    if (x1v) {
        g_A3[base + 96 + lane]  = a10;
        g_A3[base + 128 + lane] = a11;
        g_A3[base + 160 + lane] = a12;
    }
}

// ---------------- pool3 + SRM fused: warp per (b,opix,wrd), PF=8, rolling ptrs ----------------
__global__ void __launch_bounds__(512) pool3_srm() {
    int w = blockIdx.x * 16 + (threadIdx.x >> 5);
    int lane = threadIdx.x & 31;
    if (w >= NB*75) return;
    int b = w / 75, r = w % 75, pix = r / 3, wrd = r % 3;
    int y = pix / 5, x = pix % 5;
    bool xv = (2*x + 1) < 9, yv = (2*y + 1) < 9;
    const int ST = 972;                                  // words per t-plane
    const unsigned* m0 = g_M5 + b*243 + (2*y*9 + 2*x)*3 + wrd;
    const unsigned* m1 = m0 + 3;
    const unsigned* m2 = m0 + 27;
    const unsigned* m3 = m0 + 30;
    unsigned buf[8][4];
#pragma unroll
    for (int k = 0; k < 8; k++) {
        buf[k][0] = m0[k*ST];
        buf[k][1] = xv ? m1[k*ST] : 0u;
        buf[k][2] = yv ? m2[k*ST] : 0u;
        buf[k][3] = (xv && yv) ? m3[k*ST] : 0u;
    }
    const unsigned *p0 = m0 + 8*ST, *p1p = m1 + 8*ST, *p2p = m2 + 8*ST, *p3p = m3 + 8*ST;
    unsigned int* op = g_M6 + w;
    float p1 = 0, q1 = 0, p2 = 0, q2 = 0;
#pragma unroll 1
    for (int t0 = 0; t0 < 296; t0 += 8) {
#pragma unroll
        for (int k = 0; k < 8; k++) {
            int cnt = ((buf[k][0] >> lane) & 1) + ((buf[k][1] >> lane) & 1)
                    + ((buf[k][2] >> lane) & 1) + ((buf[k][3] >> lane) & 1);
            buf[k][0] = *p0; p0 += ST;
            buf[k][1] = xv ? *p1p : 0u; p1p += ST;
            buf[k][2] = yv ? *p2p : 0u; p2p += ST;
            buf[k][3] = (xv && yv) ? *p3p : 0u; p3p += ST;
            float s = srm_step(p1, q1, p2, q2, 11.0f * (float)cnt);
            unsigned bal = __ballot_sync(0xffffffffu, s > 0.5f);
            if (!lane) *op = bal;
            op += NB*75;
        }
    }
#pragma unroll
    for (int k = 0; k < 4; k++) {
        int cnt = ((buf[k][0] >> lane) & 1) + ((buf[k][1] >> lane) & 1)
                + ((buf[k][2] >> lane) & 1) + ((buf[k][3] >> lane) & 1);
        float s = srm_step(p1, q1, p2, q2, 11.0f * (float)cnt);
        unsigned bal = __ballot_sync(0xffffffffu, s > 0.5f);
        if (!lane) *op = bal;
        op += NB*75;
    }
}

// ---------------- dense1 (2400->256): WARP per (t,b), float4 weight rows ----------------
__global__ void __launch_bounds__(256) dense1() {
    int w = blockIdx.x * 8 + (threadIdx.x >> 5);
    int lane = threadIdx.x & 31;
    if (w >= TT*NB) return;
    const unsigned* m = g_M6 + (size_t)w*75;
    float4 acc0 = make_float4(0.f, 0.f, 0.f, 0.f);
    float4 acc1 = make_float4(0.f, 0.f, 0.f, 0.f);
    int pw = 0;
    for (int pos = 0; pos < 25; pos++) {
#pragma unroll
        for (int wrd = 0; wrd < 3; wrd++) {
            unsigned mm = m[pw++];
            int cb = wrd*32;
            while (mm) {
                int c = cb + __ffs(mm) - 1; mm &= mm - 1;
                const float4* wr = (const float4*)(g_Wt4 + (size_t)(c*25 + pos)*256) + lane;
                float4 v0 = wr[0], v1 = wr[32];
                acc0.x += v0.x; acc0.y += v0.y; acc0.z += v0.z; acc0.w += v0.w;
                acc1.x += v1.x; acc1.y += v1.y; acc1.z += v1.z; acc1.w += v1.w;
            }
        }
    }
    float4* op = (float4*)(g_A7 + (size_t)w*256) + lane;
    op[0]  = acc0;
    op[32] = acc1;
}

// ---------------- dense2 (256->10): warp per (t,b), writes transposed ----------------
__global__ void __launch_bounds__(256) dense2() {
    int w = blockIdx.x * 8 + (threadIdx.x >> 5);
    int lane = threadIdx.x & 31;
    if (w >= TT*NB) return;
    int t = w / NB, b = w % NB;
    if (lane < 16) {
        const unsigned* m = g_M7 + (size_t)w*8;
        float acc = 0.f;
        for (int wd = 0; wd < 8; wd++) {
            unsigned mm = m[wd];
            int ib = wd*32;
            while (mm) { int i = ib + __ffs(mm) - 1; mm &= mm - 1; acc += g_Wt5[i*16 + lane]; }
        }
        g_A8T[(size_t)(b*16 + lane)*TT + t] = acc;
    }
}

// ---------------- final SRM -> output spikes (B,10,T) ----------------
__global__ void srm_out(float* __restrict__ out) {
    int tid = threadIdx.x;
    if (tid >= 40) return;
    int b = tid / 10, o = tid % 10;
    const float* ip = g_A8T + (size_t)(b*16 + o)*TT;
    const int PF = 8;
    float buf[PF];
#pragma unroll
    for (int k = 0; k < PF; k++) buf[k] = ip[k];
    float p1 = 0, q1 = 0, p2 = 0, q2 = 0;
    float* op = out + (size_t)(b*10 + o)*TT;
    for (int t0 = 0; t0 < TT; t0 += PF) {
#pragma unroll
        for (int k = 0; k < PF; k++) {
            int t = t0 + k;
            if (t >= TT) break;
            float x = buf[k];
            int tn = t + PF;
            buf[k] = (tn < TT) ? ip[tn] : 0.f;
            op[t] = srm_step(p1, q1, p2, q2, x);
        }
    }
}

extern "C" void kernel_launch(void* const* d_in, const int* in_sizes, int n_in,
                              void* d_out, int out_size) {
    const float* s_in = (const float*)d_in[0];
    const float* Wc1  = (const float*)d_in[1];
    const float* Wc2  = (const float*)d_in[2];
    const float* Wc3  = (const float*)d_in[3];
    const float* Wd4a = (const float*)d_in[4];
    const float* Wd4b = (const float*)d_in[5];
    float* out = (float*)d_out;

    // slots 0..2 so conv1_acc lands in the profiled 4th slot
    init_weights<<<54, 256>>>(Wc1, Wc2, Wc3, Wd4b);
    pack_input<<<(NB*2*34*10 + 15)/16, 512>>>(s_in);
    prep_wt4<<<dim3(75, 8), dim3(32, 8)>>>(Wd4a);

    conv1_acc<<<(TT*NB*306 + 7)/8, 256>>>();
    srm_scan_L1<<<(NB*1156 + 15)/16, 512>>>();
    pool1_srm<<<(NB*289 + 15)/16, 512>>>();

    conv2_acc<<<(TT*NB*153 + 7)/8, 256>>>();
    srm_scan_L2<<<(NB*289*2 + 15)/16, 512>>>();
    pool2_srm<<<(NB*162 + 15)/16, 512>>>();

    conv3_acc<<<(TT*NB*45 + 7)/8, 256>>>();
    srm_scan_L3<<<(NB*81*3 + 15)/16, 512>>>();
    pool3_srm<<<(NB*75 + 15)/16, 512>>>();

    dense1<<<(TT*NB + 7)/8, 256>>>();
    srm_scan_D1<<<2, 512>>>();

    dense2<<<(TT*NB + 7)/8, 256>>>();
    srm_out<<<1, 64>>>(out);
}